// round 1
// baseline (speedup 1.0000x reference)
#include <cuda_runtime.h>
#include <math.h>

#define SEQ     2048
#define DIM     768
#define NH      12
#define HD      64
#define HIDDEN  2042
#define VOCAB   32000
#define NL      4
#define THETA   10000.0f
#define ATT_SCALE 0.125f   // 1/sqrt(64)

// ---------------- scratch (device globals; allocation-free) ----------------
__device__ float g_h [SEQ * DIM];
__device__ float g_x [SEQ * DIM];
__device__ float g_q [SEQ * DIM];
__device__ float g_k [SEQ * DIM];
__device__ float g_v [SEQ * DIM];
__device__ float g_o [SEQ * DIM];
__device__ float g_h1[SEQ * HIDDEN];
__device__ float g_h3[SEQ * HIDDEN];

// ---------------- embedding gather ----------------
__global__ void embed_kernel(const int* __restrict__ tokens,
                             const float* __restrict__ emb,
                             float* __restrict__ h) {
    int i = blockIdx.x * blockDim.x + threadIdx.x;
    if (i < SEQ * DIM) {
        int s = i / DIM, d = i - s * DIM;
        h[i] = emb[(long)tokens[s] * DIM + d];
    }
}

// ---------------- rmsnorm: one block per row ----------------
__global__ void rmsnorm_kernel(const float* __restrict__ x,
                               const float* __restrict__ w,
                               float* __restrict__ y) {
    int row = blockIdx.x;
    const float* xr = x + (long)row * DIM;
    float ss = 0.f;
    for (int d = threadIdx.x; d < DIM; d += 256) {
        float t = xr[d];
        ss += t * t;
    }
    #pragma unroll
    for (int off = 16; off; off >>= 1) ss += __shfl_xor_sync(0xffffffffu, ss, off);
    __shared__ float sred[8];
    if ((threadIdx.x & 31) == 0) sred[threadIdx.x >> 5] = ss;
    __syncthreads();
    __shared__ float s_inv;
    if (threadIdx.x == 0) {
        float tot = 0.f;
        #pragma unroll
        for (int i = 0; i < 8; i++) tot += sred[i];
        s_inv = rsqrtf(tot / (float)DIM + 1e-6f);
    }
    __syncthreads();
    float inv = s_inv;
    float* yr = y + (long)row * DIM;
    for (int d = threadIdx.x; d < DIM; d += 256)
        yr[d] = xr[d] * inv * w[d];
}

// ---------------- RoPE (in-place on q and k) ----------------
__global__ void rope_kernel(float* __restrict__ q, float* __restrict__ k) {
    int i = blockIdx.x * blockDim.x + threadIdx.x;   // over SEQ*NH*(HD/2)
    if (i >= SEQ * NH * (HD / 2)) return;
    int p  = i % (HD / 2);
    int sh = i / (HD / 2);
    int h  = sh % NH;
    int s  = sh / NH;
    float freq = powf(THETA, -(2.0f * (float)p) / (float)HD);
    float ang  = (float)s * freq;
    float c = cosf(ang), sn = sinf(ang);
    int base = s * DIM + h * HD + 2 * p;
    float a = q[base], b = q[base + 1];
    q[base]     = a * c - b * sn;
    q[base + 1] = a * sn + b * c;
    a = k[base]; b = k[base + 1];
    k[base]     = a * c - b * sn;
    k[base + 1] = a * sn + b * c;
}

// ---------------- flash attention: 1 query per warp, 16 warps/block ----------------
#define BQ 16
__global__ __launch_bounds__(32 * BQ)
void attn_kernel(const float* __restrict__ q, const float* __restrict__ k,
                 const float* __restrict__ v, float* __restrict__ o) {
    int h    = blockIdx.y;
    int q0   = blockIdx.x * BQ;
    int warp = threadIdx.x >> 5;
    int lane = threadIdx.x & 31;
    int qi   = q0 + warp;

    __shared__ float Ks[64][HD + 1];
    __shared__ float Vs[64][HD + 1];
    __shared__ float Qs[BQ][HD];

    Qs[warp][lane]      = q[(long)qi * DIM + h * HD + lane];
    Qs[warp][lane + 32] = q[(long)qi * DIM + h * HD + lane + 32];

    float m = -INFINITY, l = 0.f, o0 = 0.f, o1 = 0.f;
    int kend = q0 + BQ;   // need keys [0, kend)

    for (int t0 = 0; t0 < kend; t0 += 64) {
        __syncthreads();
        for (int idx = threadIdx.x; idx < 64 * HD; idx += 32 * BQ) {
            int kj = idx >> 6, d = idx & 63;
            long row = (long)(t0 + kj) * DIM + h * HD + d;
            Ks[kj][d] = k[row];
            Vs[kj][d] = v[row];
        }
        __syncthreads();

        float s0 = 0.f, s1 = 0.f;
        #pragma unroll
        for (int d = 0; d < HD; d++) {
            float qd = Qs[warp][d];
            s0 = fmaf(qd, Ks[lane][d],      s0);
            s1 = fmaf(qd, Ks[lane + 32][d], s1);
        }
        s0 *= ATT_SCALE; s1 *= ATT_SCALE;
        if (t0 + lane      > qi) s0 = -INFINITY;
        if (t0 + lane + 32 > qi) s1 = -INFINITY;

        float mt = fmaxf(s0, s1);
        #pragma unroll
        for (int off = 16; off; off >>= 1)
            mt = fmaxf(mt, __shfl_xor_sync(0xffffffffu, mt, off));
        float mnew  = fmaxf(m, mt);
        float alpha = expf(m - mnew);     // 0 on first tile (m=-inf)
        float p0 = expf(s0 - mnew);
        float p1 = expf(s1 - mnew);
        float lsum = p0 + p1;
        #pragma unroll
        for (int off = 16; off; off >>= 1)
            lsum += __shfl_xor_sync(0xffffffffu, lsum, off);
        l = l * alpha + lsum;
        m = mnew;
        o0 *= alpha; o1 *= alpha;

        #pragma unroll
        for (int j = 0; j < 32; j++) {
            float pa = __shfl_sync(0xffffffffu, p0, j);
            float pb = __shfl_sync(0xffffffffu, p1, j);
            o0 = fmaf(pa, Vs[j][lane],           o0);
            o0 = fmaf(pb, Vs[j + 32][lane],      o0);
            o1 = fmaf(pa, Vs[j][lane + 32],      o1);
            o1 = fmaf(pb, Vs[j + 32][lane + 32], o1);
        }
    }
    float inv = 1.f / l;
    o[(long)qi * DIM + h * HD + lane]      = o0 * inv;
    o[(long)qi * DIM + h * HD + lane + 32] = o1 * inv;
}

// ---------------- SiLU(h1) * h3 -> h1 ----------------
__global__ void silu_mul_kernel(float* __restrict__ h1, const float* __restrict__ h3) {
    int i = blockIdx.x * blockDim.x + threadIdx.x;
    if (i < SEQ * HIDDEN) {
        float a = h1[i];
        float s = a / (1.f + expf(-a));
        h1[i] = s * h3[i];
    }
}

// ---------------- GEMM: C[M,N] = A[M,K] @ B[N,K]^T (+ res), fp32 SIMT ----------------
// 128x128 tile, BK=16, 256 threads, 8x8 per thread.
__global__ __launch_bounds__(256)
void gemm_nt(const float* __restrict__ A, const float* __restrict__ B,
             const float* __restrict__ res, float* __restrict__ C,
             int M, int N, int K) {
    const int BM = 128, BN = 128, BK = 16;
    __shared__ float As[BK][BM];
    __shared__ float Bs[BK][BN];

    int bm = blockIdx.y * BM;
    int bn = blockIdx.x * BN;
    int tid = threadIdx.x;
    int tx = tid & 15, ty = tid >> 4;

    float acc[8][8];
    #pragma unroll
    for (int i = 0; i < 8; i++)
        #pragma unroll
        for (int j = 0; j < 8; j++) acc[i][j] = 0.f;

    for (int k0 = 0; k0 < K; k0 += BK) {
        // load tiles: each thread 8 consecutive k of one row
        #pragma unroll
        for (int i = 0; i < 8; i++) {
            int idx = tid * 8 + i;
            int kk = idx & 15, mm = idx >> 4;
            int gm = bm + mm, gk = k0 + kk;
            As[kk][mm] = (gm < M && gk < K) ? A[(long)gm * K + gk] : 0.f;
            int gn = bn + mm;
            Bs[kk][mm] = (gn < N && gk < K) ? B[(long)gn * K + gk] : 0.f;
        }
        __syncthreads();

        #pragma unroll
        for (int kk = 0; kk < BK; kk++) {
            float a[8], b[8];
            #pragma unroll
            for (int i = 0; i < 8; i++) a[i] = As[kk][ty * 8 + i];
            #pragma unroll
            for (int j = 0; j < 8; j++) b[j] = Bs[kk][tx * 8 + j];
            #pragma unroll
            for (int i = 0; i < 8; i++)
                #pragma unroll
                for (int j = 0; j < 8; j++)
                    acc[i][j] = fmaf(a[i], b[j], acc[i][j]);
        }
        __syncthreads();
    }

    #pragma unroll
    for (int i = 0; i < 8; i++) {
        int gm = bm + ty * 8 + i;
        if (gm >= M) continue;
        #pragma unroll
        for (int j = 0; j < 8; j++) {
            int gn = bn + tx * 8 + j;
            if (gn >= N) continue;
            float r = res ? res[(long)gm * N + gn] : 0.f;
            C[(long)gm * N + gn] = acc[i][j] + r;
        }
    }
}

// ---------------- host launcher ----------------
static inline dim3 gemm_grid(int M, int N) {
    return dim3((N + 127) / 128, (M + 127) / 128);
}

extern "C" void kernel_launch(void* const* d_in, const int* in_sizes, int n_in,
                              void* d_out, int out_size) {
    const int*   tokens   = (const int*)  d_in[0];
    const float* emb      = (const float*)d_in[1];
    const float* wq       = (const float*)d_in[2];
    const float* wk       = (const float*)d_in[3];
    const float* wv       = (const float*)d_in[4];
    const float* wo       = (const float*)d_in[5];
    const float* w1       = (const float*)d_in[6];
    const float* w2       = (const float*)d_in[7];
    const float* w3       = (const float*)d_in[8];
    const float* attn_nw  = (const float*)d_in[9];
    const float* ffn_nw   = (const float*)d_in[10];
    const float* norm_w   = (const float*)d_in[11];
    const float* out_w    = (const float*)d_in[12];
    float* out = (float*)d_out;

    float *h, *x, *q, *k, *v, *o, *h1, *h3;
    cudaGetSymbolAddress((void**)&h,  g_h);
    cudaGetSymbolAddress((void**)&x,  g_x);
    cudaGetSymbolAddress((void**)&q,  g_q);
    cudaGetSymbolAddress((void**)&k,  g_k);
    cudaGetSymbolAddress((void**)&v,  g_v);
    cudaGetSymbolAddress((void**)&o,  g_o);
    cudaGetSymbolAddress((void**)&h1, g_h1);
    cudaGetSymbolAddress((void**)&h3, g_h3);

    embed_kernel<<<(SEQ * DIM + 255) / 256, 256>>>(tokens, emb, h);

    for (int L = 0; L < NL; L++) {
        rmsnorm_kernel<<<SEQ, 256>>>(h, attn_nw + L * DIM, x);

        gemm_nt<<<gemm_grid(SEQ, DIM), 256>>>(x, wq + (long)L * DIM * DIM, nullptr, q, SEQ, DIM, DIM);
        gemm_nt<<<gemm_grid(SEQ, DIM), 256>>>(x, wk + (long)L * DIM * DIM, nullptr, k, SEQ, DIM, DIM);
        gemm_nt<<<gemm_grid(SEQ, DIM), 256>>>(x, wv + (long)L * DIM * DIM, nullptr, v, SEQ, DIM, DIM);

        rope_kernel<<<(SEQ * NH * (HD / 2) + 255) / 256, 256>>>(q, k);

        attn_kernel<<<dim3(SEQ / BQ, NH), 32 * BQ>>>(q, k, v, o);

        // h = h + o @ wo^T
        gemm_nt<<<gemm_grid(SEQ, DIM), 256>>>(o, wo + (long)L * DIM * DIM, h, h, SEQ, DIM, DIM);

        rmsnorm_kernel<<<SEQ, 256>>>(h, ffn_nw + L * DIM, x);

        gemm_nt<<<gemm_grid(SEQ, HIDDEN), 256>>>(x, w1 + (long)L * HIDDEN * DIM, nullptr, h1, SEQ, HIDDEN, DIM);
        gemm_nt<<<gemm_grid(SEQ, HIDDEN), 256>>>(x, w3 + (long)L * HIDDEN * DIM, nullptr, h3, SEQ, HIDDEN, DIM);

        silu_mul_kernel<<<(SEQ * HIDDEN + 255) / 256, 256>>>(h1, h3);

        // h = h + (silu(y1)*y3) @ w2^T   (K = HIDDEN = 2042)
        gemm_nt<<<gemm_grid(SEQ, DIM), 256>>>(h1, w2 + (long)L * DIM * HIDDEN, h, h, SEQ, DIM, HIDDEN);
    }

    rmsnorm_kernel<<<SEQ, 256>>>(h, norm_w, x);

    // logits = x @ out_w^T   [2048, 32000]
    gemm_nt<<<gemm_grid(SEQ, VOCAB), 256>>>(x, out_w, nullptr, out, SEQ, VOCAB, DIM);
}

// round 3
// speedup vs baseline: 1.4044x; 1.4044x over previous
#include <cuda_runtime.h>
#include <cuda_bf16.h>
#include <math.h>
#include <stdint.h>

#define SEQ     2048
#define DIM     768
#define NH      12
#define HD      64
#define HIDDEN  2042
#define VOCAB   32000
#define NL      4
#define THETA   10000.0f
#define ATT_SCALE 0.125f   // 1/sqrt(64)

// ---------------- scratch (device globals; allocation-free) ----------------
__device__ float g_h [SEQ * DIM];
__device__ float g_x [SEQ * DIM];
__device__ float g_q [SEQ * DIM];
__device__ float g_k [SEQ * DIM];
__device__ float g_v [SEQ * DIM];
__device__ float g_o [SEQ * DIM];
__device__ float g_h1[SEQ * HIDDEN];
__device__ float g_h3[SEQ * HIDDEN];

// ---------------- embedding gather ----------------
__global__ void embed_kernel(const int* __restrict__ tokens,
                             const float* __restrict__ emb,
                             float* __restrict__ h) {
    int i = blockIdx.x * blockDim.x + threadIdx.x;
    if (i < SEQ * DIM) {
        int s = i / DIM, d = i - s * DIM;
        h[i] = emb[(long)tokens[s] * DIM + d];
    }
}

// ---------------- rmsnorm: one block per row ----------------
__global__ void rmsnorm_kernel(const float* __restrict__ x,
                               const float* __restrict__ w,
                               float* __restrict__ y) {
    int row = blockIdx.x;
    const float* xr = x + (long)row * DIM;
    float ss = 0.f;
    for (int d = threadIdx.x; d < DIM; d += 256) {
        float t = xr[d];
        ss += t * t;
    }
    #pragma unroll
    for (int off = 16; off; off >>= 1) ss += __shfl_xor_sync(0xffffffffu, ss, off);
    __shared__ float sred[8];
    if ((threadIdx.x & 31) == 0) sred[threadIdx.x >> 5] = ss;
    __syncthreads();
    __shared__ float s_inv;
    if (threadIdx.x == 0) {
        float tot = 0.f;
        #pragma unroll
        for (int i = 0; i < 8; i++) tot += sred[i];
        s_inv = rsqrtf(tot / (float)DIM + 1e-6f);
    }
    __syncthreads();
    float inv = s_inv;
    float* yr = y + (long)row * DIM;
    for (int d = threadIdx.x; d < DIM; d += 256)
        yr[d] = xr[d] * inv * w[d];
}

// ---------------- RoPE (in-place on q and k) ----------------
__global__ void rope_kernel(float* __restrict__ q, float* __restrict__ k) {
    int i = blockIdx.x * blockDim.x + threadIdx.x;   // over SEQ*NH*(HD/2)
    if (i >= SEQ * NH * (HD / 2)) return;
    int p  = i % (HD / 2);
    int sh = i / (HD / 2);
    int h  = sh % NH;
    int s  = sh / NH;
    float freq = powf(THETA, -(2.0f * (float)p) / (float)HD);
    float ang  = (float)s * freq;
    float c = cosf(ang), sn = sinf(ang);
    int base = s * DIM + h * HD + 2 * p;
    float a = q[base], b = q[base + 1];
    q[base]     = a * c - b * sn;
    q[base + 1] = a * sn + b * c;
    a = k[base]; b = k[base + 1];
    k[base]     = a * c - b * sn;
    k[base + 1] = a * sn + b * c;
}

// ---------------- flash attention: 1 query per warp, 16 warps/block ----------------
#define BQ 16
__global__ __launch_bounds__(32 * BQ)
void attn_kernel(const float* __restrict__ q, const float* __restrict__ k,
                 const float* __restrict__ v, float* __restrict__ o) {
    int h    = blockIdx.y;
    int q0   = blockIdx.x * BQ;
    int warp = threadIdx.x >> 5;
    int lane = threadIdx.x & 31;
    int qi   = q0 + warp;

    __shared__ float Ks[64][HD + 1];
    __shared__ float Vs[64][HD + 1];
    __shared__ float Qs[BQ][HD];

    Qs[warp][lane]      = q[(long)qi * DIM + h * HD + lane];
    Qs[warp][lane + 32] = q[(long)qi * DIM + h * HD + lane + 32];

    float m = -INFINITY, l = 0.f, o0 = 0.f, o1 = 0.f;
    int kend = q0 + BQ;

    for (int t0 = 0; t0 < kend; t0 += 64) {
        __syncthreads();
        for (int idx = threadIdx.x; idx < 64 * HD; idx += 32 * BQ) {
            int kj = idx >> 6, d = idx & 63;
            long row = (long)(t0 + kj) * DIM + h * HD + d;
            Ks[kj][d] = k[row];
            Vs[kj][d] = v[row];
        }
        __syncthreads();

        float s0 = 0.f, s1 = 0.f;
        #pragma unroll
        for (int d = 0; d < HD; d++) {
            float qd = Qs[warp][d];
            s0 = fmaf(qd, Ks[lane][d],      s0);
            s1 = fmaf(qd, Ks[lane + 32][d], s1);
        }
        s0 *= ATT_SCALE; s1 *= ATT_SCALE;
        if (t0 + lane      > qi) s0 = -INFINITY;
        if (t0 + lane + 32 > qi) s1 = -INFINITY;

        float mt = fmaxf(s0, s1);
        #pragma unroll
        for (int off = 16; off; off >>= 1)
            mt = fmaxf(mt, __shfl_xor_sync(0xffffffffu, mt, off));
        float mnew  = fmaxf(m, mt);
        float alpha = expf(m - mnew);
        float p0 = expf(s0 - mnew);
        float p1 = expf(s1 - mnew);
        float lsum = p0 + p1;
        #pragma unroll
        for (int off = 16; off; off >>= 1)
            lsum += __shfl_xor_sync(0xffffffffu, lsum, off);
        l = l * alpha + lsum;
        m = mnew;
        o0 *= alpha; o1 *= alpha;

        #pragma unroll
        for (int j = 0; j < 32; j++) {
            float pa = __shfl_sync(0xffffffffu, p0, j);
            float pb = __shfl_sync(0xffffffffu, p1, j);
            o0 = fmaf(pa, Vs[j][lane],           o0);
            o0 = fmaf(pb, Vs[j + 32][lane],      o0);
            o1 = fmaf(pa, Vs[j][lane + 32],      o1);
            o1 = fmaf(pb, Vs[j + 32][lane + 32], o1);
        }
    }
    float inv = 1.f / l;
    o[(long)qi * DIM + h * HD + lane]      = o0 * inv;
    o[(long)qi * DIM + h * HD + lane + 32] = o1 * inv;
}

// ---------------- SiLU(h1) * h3 -> h1 ----------------
__global__ void silu_mul_kernel(float* __restrict__ h1, const float* __restrict__ h3) {
    int i = blockIdx.x * blockDim.x + threadIdx.x;
    if (i < SEQ * HIDDEN) {
        float a = h1[i];
        float s = a / (1.f + expf(-a));
        h1[i] = s * h3[i];
    }
}

// ================= bf16x3 tensor-core GEMM: C = A @ B^T (+ res) =================
// Split each fp32 input into hi+lo bf16; compute hi*hi + hi*lo + lo*hi with
// mma.m16n8k16 (fp32 accumulate). 128x128x16 tile, 256 threads, warp tile 64x32.
#define TBM 128
#define TBN 128
#define TBK 16
#define SMS (TBM + 8)   // row stride in u32: 136 -> conflict-free frag LDS

__device__ __forceinline__ void mma_bf16(float* d, const uint32_t* a, const uint32_t* b) {
    asm volatile(
        "mma.sync.aligned.m16n8k16.row.col.f32.bf16.bf16.f32 "
        "{%0,%1,%2,%3}, {%4,%5,%6,%7}, {%8,%9}, {%0,%1,%2,%3};"
        : "+f"(d[0]), "+f"(d[1]), "+f"(d[2]), "+f"(d[3])
        : "r"(a[0]), "r"(a[1]), "r"(a[2]), "r"(a[3]), "r"(b[0]), "r"(b[1]));
}

__device__ __forceinline__ void split2(float x0, float x1, uint32_t& hi, uint32_t& lo) {
    __nv_bfloat16 h0 = __float2bfloat16(x0);
    __nv_bfloat16 h1 = __float2bfloat16(x1);
    __nv_bfloat16 l0 = __float2bfloat16(x0 - __bfloat162float(h0));
    __nv_bfloat16 l1 = __float2bfloat16(x1 - __bfloat162float(h1));
    __nv_bfloat162 hp = __halves2bfloat162(h0, h1);
    __nv_bfloat162 lp = __halves2bfloat162(l0, l1);
    hi = *reinterpret_cast<uint32_t*>(&hp);
    lo = *reinterpret_cast<uint32_t*>(&lp);
}

__global__ __launch_bounds__(256)
void gemm_tc(const float* __restrict__ A, const float* __restrict__ B,
             const float* __restrict__ res, float* __restrict__ C,
             int M, int N, int K) {
    // [kp][row] where kp indexes k-pairs (8 pairs per 16-k tile)
    __shared__ uint32_t AsH[8][SMS];
    __shared__ uint32_t AsL[8][SMS];
    __shared__ uint32_t BsH[8][SMS];
    __shared__ uint32_t BsL[8][SMS];

    int bm = blockIdx.y * TBM;
    int bn = blockIdx.x * TBN;
    int tid  = threadIdx.x;
    int warp = tid >> 5, lane = tid & 31;
    int wm = (warp >> 2) * 64;     // warp m offset
    int wn = (warp & 3) * 32;      // warp n offset
    int g  = lane >> 2;            // 0-7
    int tg = lane & 3;             // 0-3

    float acc[4][4][4];
    #pragma unroll
    for (int mi = 0; mi < 4; mi++)
        #pragma unroll
        for (int ni = 0; ni < 4; ni++)
            #pragma unroll
            for (int r = 0; r < 4; r++) acc[mi][ni][r] = 0.f;

    // loader: thread covers row lr, k-range [lk, lk+8) -> kp range [lk/2, lk/2+4)
    int lr = tid >> 1;
    int lk = (tid & 1) * 8;
    int kp0 = lk >> 1;
    const float* Arow = A + (long)(bm + lr) * K;
    const float* Brow = B + (long)(bn + lr) * K;
    bool bvalid = (bn + lr) < N;

    float ra[8], rb[8];
    #pragma unroll
    for (int i = 0; i < 8; i++) {
        int gk = lk + i;
        ra[i] = (gk < K) ? Arow[gk] : 0.f;
        rb[i] = (gk < K && bvalid) ? Brow[gk] : 0.f;
    }

    for (int k0 = 0; k0 < K; k0 += TBK) {
        // stage registers -> smem (split hi/lo)
        #pragma unroll
        for (int p = 0; p < 4; p++) {
            uint32_t hi, lo;
            split2(ra[2 * p], ra[2 * p + 1], hi, lo);
            AsH[kp0 + p][lr] = hi; AsL[kp0 + p][lr] = lo;
            split2(rb[2 * p], rb[2 * p + 1], hi, lo);
            BsH[kp0 + p][lr] = hi; BsL[kp0 + p][lr] = lo;
        }
        __syncthreads();

        // prefetch next tile (overlaps mma)
        if (k0 + TBK < K) {
            #pragma unroll
            for (int i = 0; i < 8; i++) {
                int gk = k0 + TBK + lk + i;
                ra[i] = (gk < K) ? Arow[gk] : 0.f;
                rb[i] = (gk < K && bvalid) ? Brow[gk] : 0.f;
            }
        }

        uint32_t afH[4][4], afL[4][4], bfH[4][2], bfL[4][2];
        #pragma unroll
        for (int mi = 0; mi < 4; mi++) {
            int mrow = wm + mi * 16 + g;
            afH[mi][0] = AsH[tg    ][mrow];     afL[mi][0] = AsL[tg    ][mrow];
            afH[mi][1] = AsH[tg    ][mrow + 8]; afL[mi][1] = AsL[tg    ][mrow + 8];
            afH[mi][2] = AsH[tg + 4][mrow];     afL[mi][2] = AsL[tg + 4][mrow];
            afH[mi][3] = AsH[tg + 4][mrow + 8]; afL[mi][3] = AsL[tg + 4][mrow + 8];
        }
        #pragma unroll
        for (int ni = 0; ni < 4; ni++) {
            int ncol = wn + ni * 8 + g;
            bfH[ni][0] = BsH[tg    ][ncol];  bfL[ni][0] = BsL[tg    ][ncol];
            bfH[ni][1] = BsH[tg + 4][ncol];  bfL[ni][1] = BsL[tg + 4][ncol];
        }
        #pragma unroll
        for (int mi = 0; mi < 4; mi++)
            #pragma unroll
            for (int ni = 0; ni < 4; ni++) {
                mma_bf16(acc[mi][ni], afL[mi], bfH[ni]);   // lo*hi
                mma_bf16(acc[mi][ni], afH[mi], bfL[ni]);   // hi*lo
                mma_bf16(acc[mi][ni], afH[mi], bfH[ni]);   // hi*hi
            }
        __syncthreads();
    }

    // epilogue: c0,c1 -> row g, cols tg*2..+1; c2,c3 -> row g+8
    #pragma unroll
    for (int mi = 0; mi < 4; mi++) {
        int r0 = bm + wm + mi * 16 + g;
        #pragma unroll
        for (int ni = 0; ni < 4; ni++) {
            int c0 = bn + wn + ni * 8 + tg * 2;
            #pragma unroll
            for (int half = 0; half < 2; half++) {
                int row = r0 + half * 8;
                float v0 = acc[mi][ni][half * 2 + 0];
                float v1 = acc[mi][ni][half * 2 + 1];
                if (c0 < N) {
                    long idx = (long)row * N + c0;
                    C[idx] = v0 + (res ? res[idx] : 0.f);
                }
                if (c0 + 1 < N) {
                    long idx = (long)row * N + c0 + 1;
                    C[idx] = v1 + (res ? res[idx] : 0.f);
                }
            }
        }
    }
}

// ---------------- host launcher ----------------
static inline dim3 gemm_grid(int M, int N) {
    return dim3((N + TBN - 1) / TBN, (M + TBM - 1) / TBM);
}

extern "C" void kernel_launch(void* const* d_in, const int* in_sizes, int n_in,
                              void* d_out, int out_size) {
    const int*   tokens   = (const int*)  d_in[0];
    const float* emb      = (const float*)d_in[1];
    const float* wq       = (const float*)d_in[2];
    const float* wk       = (const float*)d_in[3];
    const float* wv       = (const float*)d_in[4];
    const float* wo       = (const float*)d_in[5];
    const float* w1       = (const float*)d_in[6];
    const float* w2       = (const float*)d_in[7];
    const float* w3       = (const float*)d_in[8];
    const float* attn_nw  = (const float*)d_in[9];
    const float* ffn_nw   = (const float*)d_in[10];
    const float* norm_w   = (const float*)d_in[11];
    const float* out_w    = (const float*)d_in[12];
    float* out = (float*)d_out;

    float *h, *x, *q, *k, *v, *o, *h1, *h3;
    cudaGetSymbolAddress((void**)&h,  g_h);
    cudaGetSymbolAddress((void**)&x,  g_x);
    cudaGetSymbolAddress((void**)&q,  g_q);
    cudaGetSymbolAddress((void**)&k,  g_k);
    cudaGetSymbolAddress((void**)&v,  g_v);
    cudaGetSymbolAddress((void**)&o,  g_o);
    cudaGetSymbolAddress((void**)&h1, g_h1);
    cudaGetSymbolAddress((void**)&h3, g_h3);

    embed_kernel<<<(SEQ * DIM + 255) / 256, 256>>>(tokens, emb, h);

    for (int L = 0; L < NL; L++) {
        rmsnorm_kernel<<<SEQ, 256>>>(h, attn_nw + L * DIM, x);

        gemm_tc<<<gemm_grid(SEQ, DIM), 256>>>(x, wq + (long)L * DIM * DIM, nullptr, q, SEQ, DIM, DIM);
        gemm_tc<<<gemm_grid(SEQ, DIM), 256>>>(x, wk + (long)L * DIM * DIM, nullptr, k, SEQ, DIM, DIM);
        gemm_tc<<<gemm_grid(SEQ, DIM), 256>>>(x, wv + (long)L * DIM * DIM, nullptr, v, SEQ, DIM, DIM);

        rope_kernel<<<(SEQ * NH * (HD / 2) + 255) / 256, 256>>>(q, k);

        attn_kernel<<<dim3(SEQ / BQ, NH), 32 * BQ>>>(q, k, v, o);

        gemm_tc<<<gemm_grid(SEQ, DIM), 256>>>(o, wo + (long)L * DIM * DIM, h, h, SEQ, DIM, DIM);

        rmsnorm_kernel<<<SEQ, 256>>>(h, ffn_nw + L * DIM, x);

        gemm_tc<<<gemm_grid(SEQ, HIDDEN), 256>>>(x, w1 + (long)L * HIDDEN * DIM, nullptr, h1, SEQ, HIDDEN, DIM);
        gemm_tc<<<gemm_grid(SEQ, HIDDEN), 256>>>(x, w3 + (long)L * HIDDEN * DIM, nullptr, h3, SEQ, HIDDEN, DIM);

        silu_mul_kernel<<<(SEQ * HIDDEN + 255) / 256, 256>>>(h1, h3);

        gemm_tc<<<gemm_grid(SEQ, DIM), 256>>>(h1, w2 + (long)L * DIM * HIDDEN, h, h, SEQ, DIM, HIDDEN);
    }

    rmsnorm_kernel<<<SEQ, 256>>>(h, norm_w, x);

    gemm_tc<<<gemm_grid(SEQ, VOCAB), 256>>>(x, out_w, nullptr, out, SEQ, VOCAB, DIM);
}

// round 4
// speedup vs baseline: 2.1043x; 1.4984x over previous
#include <cuda_runtime.h>
#include <cuda_bf16.h>
#include <math.h>
#include <stdint.h>

#define SEQ     2048
#define DIM     768
#define NH      12
#define HD      64
#define HIDDEN  2042
#define HIDP    2048          // padded hidden (K mult of 32)
#define N13     4096          // fused w1||w3 N (each half padded to 2048)
#define QKVN    2304          // fused q|k|v N
#define VOCAB   32000
#define NL      4
#define THETA   10000.0f
#define ATT_SCALE 0.125f

typedef __nv_bfloat16 bf16;

// ---------------- fp32 scratch ----------------
__device__ float g_h  [SEQ * DIM];
__device__ float g_x  [SEQ * DIM];
__device__ float g_qkv[SEQ * QKVN];
__device__ float g_o  [SEQ * DIM];
__device__ float g_g  [SEQ * N13];     // w1||w3 output
__device__ float g_h1 [SEQ * HIDP];    // silu result, pad cols zero

// ---------------- bf16 hi/lo planes ----------------
__device__ bf16 g_wqkv_h[NL * QKVN * DIM],  g_wqkv_l[NL * QKVN * DIM];
__device__ bf16 g_wo_h  [NL * DIM * DIM],   g_wo_l  [NL * DIM * DIM];
__device__ bf16 g_w13_h [NL * N13 * DIM],   g_w13_l [NL * N13 * DIM];
__device__ bf16 g_w2_h  [NL * DIM * HIDP],  g_w2_l  [NL * DIM * HIDP];
__device__ bf16 g_ow_h  [VOCAB * DIM],      g_ow_l  [VOCAB * DIM];
__device__ bf16 g_xh [SEQ * DIM],  g_xl [SEQ * DIM];
__device__ bf16 g_oh [SEQ * DIM],  g_ol [SEQ * DIM];
__device__ bf16 g_h1h[SEQ * HIDP], g_h1l[SEQ * HIDP];

// ---------------- split fp32 -> hi/lo bf16 planes (with K padding) ----------------
__global__ void split_kernel(const float* __restrict__ src,
                             bf16* __restrict__ dh, bf16* __restrict__ dl,
                             int rows, int Ks, int Kd) {
    long i = (long)blockIdx.x * blockDim.x + threadIdx.x;
    if (i >= (long)rows * Kd) return;
    int r = (int)(i / Kd), c = (int)(i - (long)r * Kd);
    float v = (c < Ks) ? src[(long)r * Ks + c] : 0.f;
    bf16 h = __float2bfloat16(v);
    dh[i] = h;
    dl[i] = __float2bfloat16(v - __bfloat162float(h));
}

// ---------------- embedding ----------------
__global__ void embed_kernel(const int* __restrict__ tokens,
                             const float* __restrict__ emb,
                             float* __restrict__ h) {
    int i = blockIdx.x * blockDim.x + threadIdx.x;
    if (i < SEQ * DIM) {
        int s = i / DIM, d = i - s * DIM;
        h[i] = emb[(long)tokens[s] * DIM + d];
    }
}

// ---------------- rmsnorm ----------------
__global__ void rmsnorm_kernel(const float* __restrict__ x,
                               const float* __restrict__ w,
                               float* __restrict__ y) {
    int row = blockIdx.x;
    const float* xr = x + (long)row * DIM;
    float ss = 0.f;
    for (int d = threadIdx.x; d < DIM; d += 256) { float t = xr[d]; ss += t * t; }
    #pragma unroll
    for (int off = 16; off; off >>= 1) ss += __shfl_xor_sync(0xffffffffu, ss, off);
    __shared__ float sred[8];
    if ((threadIdx.x & 31) == 0) sred[threadIdx.x >> 5] = ss;
    __syncthreads();
    __shared__ float s_inv;
    if (threadIdx.x == 0) {
        float tot = 0.f;
        #pragma unroll
        for (int i = 0; i < 8; i++) tot += sred[i];
        s_inv = rsqrtf(tot / (float)DIM + 1e-6f);
    }
    __syncthreads();
    float inv = s_inv;
    float* yr = y + (long)row * DIM;
    for (int d = threadIdx.x; d < DIM; d += 256) yr[d] = xr[d] * inv * w[d];
}

// ---------------- RoPE on fused qkv (q at col 0, k at col DIM) ----------------
__global__ void rope_kernel(float* __restrict__ qkv) {
    int i = blockIdx.x * blockDim.x + threadIdx.x;
    if (i >= SEQ * NH * (HD / 2)) return;
    int p  = i % (HD / 2);
    int sh = i / (HD / 2);
    int h  = sh % NH;
    int s  = sh / NH;
    float freq = powf(THETA, -(2.0f * (float)p) / (float)HD);
    float ang  = (float)s * freq;
    float c = cosf(ang), sn = sinf(ang);
    long base = (long)s * QKVN + h * HD + 2 * p;
    float a = qkv[base], b = qkv[base + 1];
    qkv[base]     = a * c - b * sn;
    qkv[base + 1] = a * sn + b * c;
    a = qkv[base + DIM]; b = qkv[base + DIM + 1];
    qkv[base + DIM]     = a * c - b * sn;
    qkv[base + DIM + 1] = a * sn + b * c;
}

// ---------------- flash attention (reads fused qkv) ----------------
#define BQ 16
__global__ __launch_bounds__(32 * BQ)
void attn_kernel(const float* __restrict__ qkv, float* __restrict__ o) {
    int h    = blockIdx.y;
    int q0   = blockIdx.x * BQ;
    int warp = threadIdx.x >> 5;
    int lane = threadIdx.x & 31;
    int qi   = q0 + warp;

    __shared__ float Ks[64][HD + 1];
    __shared__ float Vs[64][HD + 1];
    __shared__ float Qs[BQ][HD];

    Qs[warp][lane]      = qkv[(long)qi * QKVN + h * HD + lane];
    Qs[warp][lane + 32] = qkv[(long)qi * QKVN + h * HD + lane + 32];

    float m = -INFINITY, l = 0.f, o0 = 0.f, o1 = 0.f;
    int kend = q0 + BQ;

    for (int t0 = 0; t0 < kend; t0 += 64) {
        __syncthreads();
        for (int idx = threadIdx.x; idx < 64 * HD; idx += 32 * BQ) {
            int kj = idx >> 6, d = idx & 63;
            long row = (long)(t0 + kj) * QKVN + h * HD + d;
            Ks[kj][d] = qkv[row + DIM];
            Vs[kj][d] = qkv[row + 2 * DIM];
        }
        __syncthreads();

        float s0 = 0.f, s1 = 0.f;
        #pragma unroll
        for (int d = 0; d < HD; d++) {
            float qd = Qs[warp][d];
            s0 = fmaf(qd, Ks[lane][d],      s0);
            s1 = fmaf(qd, Ks[lane + 32][d], s1);
        }
        s0 *= ATT_SCALE; s1 *= ATT_SCALE;
        if (t0 + lane      > qi) s0 = -INFINITY;
        if (t0 + lane + 32 > qi) s1 = -INFINITY;

        float mt = fmaxf(s0, s1);
        #pragma unroll
        for (int off = 16; off; off >>= 1)
            mt = fmaxf(mt, __shfl_xor_sync(0xffffffffu, mt, off));
        float mnew  = fmaxf(m, mt);
        float alpha = expf(m - mnew);
        float p0 = expf(s0 - mnew);
        float p1 = expf(s1 - mnew);
        float lsum = p0 + p1;
        #pragma unroll
        for (int off = 16; off; off >>= 1)
            lsum += __shfl_xor_sync(0xffffffffu, lsum, off);
        l = l * alpha + lsum;
        m = mnew;
        o0 *= alpha; o1 *= alpha;

        #pragma unroll
        for (int j = 0; j < 32; j++) {
            float pa = __shfl_sync(0xffffffffu, p0, j);
            float pb = __shfl_sync(0xffffffffu, p1, j);
            o0 = fmaf(pa, Vs[j][lane],           o0);
            o0 = fmaf(pb, Vs[j + 32][lane],      o0);
            o1 = fmaf(pa, Vs[j][lane + 32],      o1);
            o1 = fmaf(pb, Vs[j + 32][lane + 32], o1);
        }
    }
    float inv = 1.f / l;
    o[(long)qi * DIM + h * HD + lane]      = o0 * inv;
    o[(long)qi * DIM + h * HD + lane + 32] = o1 * inv;
}

// ---------------- SiLU(g[:, :2042]) * g[:, 2048:4090] -> h1 [SEQ][HIDP] ----------------
__global__ void silu_mul_kernel(const float* __restrict__ gg, float* __restrict__ h1) {
    int i = blockIdx.x * blockDim.x + threadIdx.x;
    if (i < SEQ * HIDDEN) {
        int s = i / HIDDEN, j = i - s * HIDDEN;
        float a = gg[(long)s * N13 + j];
        float b = gg[(long)s * N13 + HIDP + j];
        float sl = a / (1.f + expf(-a));
        h1[(long)s * HIDP + j] = sl * b;
    }
}

// ================= bf16x3 GEMM, preconverted planes, cp.async double-buffered =================
// C[M,N] = A@B^T (+res). M%128==0, N%128==0, K%32==0 (guard-free).
// 128x128x32 tile, 256 threads, warp tile 64x32, mma m16n8k16.
#define PLANE 2560            // u32 per plane: 128 rows * 20
#define STAGEU (4 * PLANE)    // u32 per stage (AH, AL, BH, BL)
#define GSMEM (2 * STAGEU * 4)  // bytes: 81920

__device__ __forceinline__ void mma_bf16(float* d, const uint32_t* a, const uint32_t* b) {
    asm volatile(
        "mma.sync.aligned.m16n8k16.row.col.f32.bf16.bf16.f32 "
        "{%0,%1,%2,%3}, {%4,%5,%6,%7}, {%8,%9}, {%0,%1,%2,%3};"
        : "+f"(d[0]), "+f"(d[1]), "+f"(d[2]), "+f"(d[3])
        : "r"(a[0]), "r"(a[1]), "r"(a[2]), "r"(a[3]), "r"(b[0]), "r"(b[1]));
}

__device__ __forceinline__ void cpa16(uint32_t dst, const void* src) {
    asm volatile("cp.async.ca.shared.global [%0], [%1], 16;" :: "r"(dst), "l"(src));
}

__global__ __launch_bounds__(256, 2)
void gemm_bf3(const bf16* __restrict__ Ah, const bf16* __restrict__ Al,
              const bf16* __restrict__ Bh, const bf16* __restrict__ Bl,
              const float* __restrict__ res, float* __restrict__ C,
              int M, int N, int K) {
    extern __shared__ uint32_t sm[];
    int bm = blockIdx.y * 128;
    int bn = blockIdx.x * 128;
    int tid = threadIdx.x;
    int warp = tid >> 5, lane = tid & 31;
    int wm = (warp >> 2) * 64;
    int wn = (warp & 3) * 32;
    int g = lane >> 2, tg = lane & 3;

    uint32_t sbase = (uint32_t)__cvta_generic_to_shared(sm);

    // loader: 2 chunks (16B each) per plane per thread; chunk c -> row c>>2, kchunk c&3
    int c0 = tid * 2, c1 = tid * 2 + 1;
    int r0 = c0 >> 2, kc0 = c0 & 3;
    int r1 = c1 >> 2, kc1 = c1 & 3;
    uint32_t so0 = (uint32_t)(r0 * 20 + kc0 * 4) * 4;
    uint32_t so1 = (uint32_t)(r1 * 20 + kc1 * 4) * 4;

    float acc[4][4][4];
    #pragma unroll
    for (int mi = 0; mi < 4; mi++)
        #pragma unroll
        for (int ni = 0; ni < 4; ni++)
            #pragma unroll
            for (int r = 0; r < 4; r++) acc[mi][ni][r] = 0.f;

    const bf16* gP[4] = {Ah, Al, Bh, Bl};
    long rowA0 = (long)(bm + r0) * K, rowA1 = (long)(bm + r1) * K;
    long rowB0 = (long)(bn + r0) * K, rowB1 = (long)(bn + r1) * K;

    int KT = K / 32;

    // prologue: stage 0
    {
        int k0 = 0;
        #pragma unroll
        for (int p = 0; p < 4; p++) {
            long ro0 = (p < 2) ? rowA0 : rowB0;
            long ro1 = (p < 2) ? rowA1 : rowB1;
            uint32_t d = sbase + (uint32_t)p * PLANE * 4;
            cpa16(d + so0, gP[p] + ro0 + k0 + kc0 * 8);
            cpa16(d + so1, gP[p] + ro1 + k0 + kc1 * 8);
        }
        asm volatile("cp.async.commit_group;");
    }

    for (int kt = 0; kt < KT; kt++) {
        asm volatile("cp.async.wait_group 0;");
        __syncthreads();

        if (kt + 1 < KT) {
            int s = (kt + 1) & 1;
            int k0 = (kt + 1) * 32;
            uint32_t st = sbase + (uint32_t)s * STAGEU * 4;
            #pragma unroll
            for (int p = 0; p < 4; p++) {
                long ro0 = (p < 2) ? rowA0 : rowB0;
                long ro1 = (p < 2) ? rowA1 : rowB1;
                uint32_t d = st + (uint32_t)p * PLANE * 4;
                cpa16(d + so0, gP[p] + ro0 + k0 + kc0 * 8);
                cpa16(d + so1, gP[p] + ro1 + k0 + kc1 * 8);
            }
            asm volatile("cp.async.commit_group;");
        }

        const uint32_t* AH = sm + (kt & 1) * STAGEU;
        const uint32_t* AL = AH + PLANE;
        const uint32_t* BH = AL + PLANE;
        const uint32_t* BL = BH + PLANE;

        #pragma unroll
        for (int ks = 0; ks < 2; ks++) {
            int cc = ks * 8;
            uint32_t af[4][4], bf[4][2];
            // hi*hi
            #pragma unroll
            for (int mi = 0; mi < 4; mi++) {
                int mr = wm + mi * 16 + g;
                af[mi][0] = AH[mr * 20 + cc + tg];
                af[mi][1] = AH[(mr + 8) * 20 + cc + tg];
                af[mi][2] = AH[mr * 20 + cc + tg + 4];
                af[mi][3] = AH[(mr + 8) * 20 + cc + tg + 4];
            }
            #pragma unroll
            for (int ni = 0; ni < 4; ni++) {
                int nc = wn + ni * 8 + g;
                bf[ni][0] = BH[nc * 20 + cc + tg];
                bf[ni][1] = BH[nc * 20 + cc + tg + 4];
            }
            #pragma unroll
            for (int mi = 0; mi < 4; mi++)
                #pragma unroll
                for (int ni = 0; ni < 4; ni++)
                    mma_bf16(acc[mi][ni], af[mi], bf[ni]);
            // hiA * loB
            #pragma unroll
            for (int ni = 0; ni < 4; ni++) {
                int nc = wn + ni * 8 + g;
                bf[ni][0] = BL[nc * 20 + cc + tg];
                bf[ni][1] = BL[nc * 20 + cc + tg + 4];
            }
            #pragma unroll
            for (int mi = 0; mi < 4; mi++)
                #pragma unroll
                for (int ni = 0; ni < 4; ni++)
                    mma_bf16(acc[mi][ni], af[mi], bf[ni]);
            // loA * hiB
            #pragma unroll
            for (int mi = 0; mi < 4; mi++) {
                int mr = wm + mi * 16 + g;
                af[mi][0] = AL[mr * 20 + cc + tg];
                af[mi][1] = AL[(mr + 8) * 20 + cc + tg];
                af[mi][2] = AL[mr * 20 + cc + tg + 4];
                af[mi][3] = AL[(mr + 8) * 20 + cc + tg + 4];
            }
            #pragma unroll
            for (int ni = 0; ni < 4; ni++) {
                int nc = wn + ni * 8 + g;
                bf[ni][0] = BH[nc * 20 + cc + tg];
                bf[ni][1] = BH[nc * 20 + cc + tg + 4];
            }
            #pragma unroll
            for (int mi = 0; mi < 4; mi++)
                #pragma unroll
                for (int ni = 0; ni < 4; ni++)
                    mma_bf16(acc[mi][ni], af[mi], bf[ni]);
        }
    }

    // epilogue (guard-free: N multiple of 128)
    #pragma unroll
    for (int mi = 0; mi < 4; mi++) {
        int row0 = bm + wm + mi * 16 + g;
        #pragma unroll
        for (int ni = 0; ni < 4; ni++) {
            int col = bn + wn + ni * 8 + tg * 2;
            #pragma unroll
            for (int half = 0; half < 2; half++) {
                int row = row0 + half * 8;
                long idx = (long)row * N + col;
                float v0 = acc[mi][ni][half * 2 + 0];
                float v1 = acc[mi][ni][half * 2 + 1];
                if (res) { v0 += res[idx]; v1 += res[idx + 1]; }
                C[idx]     = v0;
                C[idx + 1] = v1;
            }
        }
    }
}

// ---------------- host launcher ----------------
static inline dim3 ggrid(int M, int N) { return dim3(N / 128, M / 128); }

static inline void split_launch(const float* src, bf16* dh, bf16* dl,
                                int rows, int Ks, int Kd) {
    long n = (long)rows * Kd;
    split_kernel<<<(unsigned)((n + 255) / 256), 256>>>(src, dh, dl, rows, Ks, Kd);
}

extern "C" void kernel_launch(void* const* d_in, const int* in_sizes, int n_in,
                              void* d_out, int out_size) {
    const int*   tokens   = (const int*)  d_in[0];
    const float* emb      = (const float*)d_in[1];
    const float* wq       = (const float*)d_in[2];
    const float* wk       = (const float*)d_in[3];
    const float* wv       = (const float*)d_in[4];
    const float* wo       = (const float*)d_in[5];
    const float* w1       = (const float*)d_in[6];
    const float* w2       = (const float*)d_in[7];
    const float* w3       = (const float*)d_in[8];
    const float* attn_nw  = (const float*)d_in[9];
    const float* ffn_nw   = (const float*)d_in[10];
    const float* norm_w   = (const float*)d_in[11];
    const float* out_w    = (const float*)d_in[12];
    float* out = (float*)d_out;

    float *h, *x, *qkv, *o, *gg, *h1;
    cudaGetSymbolAddress((void**)&h,   g_h);
    cudaGetSymbolAddress((void**)&x,   g_x);
    cudaGetSymbolAddress((void**)&qkv, g_qkv);
    cudaGetSymbolAddress((void**)&o,   g_o);
    cudaGetSymbolAddress((void**)&gg,  g_g);
    cudaGetSymbolAddress((void**)&h1,  g_h1);

    bf16 *wqkvh, *wqkvl, *woh, *wol, *w13h, *w13l, *w2h, *w2l, *owh, *owl;
    bf16 *xh, *xl, *oh, *ol, *h1h, *h1l;
    cudaGetSymbolAddress((void**)&wqkvh, g_wqkv_h); cudaGetSymbolAddress((void**)&wqkvl, g_wqkv_l);
    cudaGetSymbolAddress((void**)&woh,   g_wo_h);   cudaGetSymbolAddress((void**)&wol,   g_wo_l);
    cudaGetSymbolAddress((void**)&w13h,  g_w13_h);  cudaGetSymbolAddress((void**)&w13l,  g_w13_l);
    cudaGetSymbolAddress((void**)&w2h,   g_w2_h);   cudaGetSymbolAddress((void**)&w2l,   g_w2_l);
    cudaGetSymbolAddress((void**)&owh,   g_ow_h);   cudaGetSymbolAddress((void**)&owl,   g_ow_l);
    cudaGetSymbolAddress((void**)&xh,  g_xh);  cudaGetSymbolAddress((void**)&xl,  g_xl);
    cudaGetSymbolAddress((void**)&oh,  g_oh);  cudaGetSymbolAddress((void**)&ol,  g_ol);
    cudaGetSymbolAddress((void**)&h1h, g_h1h); cudaGetSymbolAddress((void**)&h1l, g_h1l);

    cudaFuncSetAttribute(gemm_bf3, cudaFuncAttributeMaxDynamicSharedMemorySize, GSMEM);

    // ---- weight conversion (every launch; deterministic) ----
    for (int L = 0; L < NL; L++) {
        long wOff = (long)L * DIM * DIM;
        split_launch(wq + wOff, wqkvh + ((long)L * QKVN + 0)    * DIM,
                                wqkvl + ((long)L * QKVN + 0)    * DIM, DIM, DIM, DIM);
        split_launch(wk + wOff, wqkvh + ((long)L * QKVN + DIM)  * DIM,
                                wqkvl + ((long)L * QKVN + DIM)  * DIM, DIM, DIM, DIM);
        split_launch(wv + wOff, wqkvh + ((long)L * QKVN + 2*DIM)* DIM,
                                wqkvl + ((long)L * QKVN + 2*DIM)* DIM, DIM, DIM, DIM);
        split_launch(wo + wOff, woh + wOff, wol + wOff, DIM, DIM, DIM);
        long w1Off = (long)L * HIDDEN * DIM;
        split_launch(w1 + w1Off, w13h + (long)L * N13 * DIM,
                                 w13l + (long)L * N13 * DIM, HIDDEN, DIM, DIM);
        split_launch(w3 + w1Off, w13h + ((long)L * N13 + HIDP) * DIM,
                                 w13l + ((long)L * N13 + HIDP) * DIM, HIDDEN, DIM, DIM);
        split_launch(w2 + (long)L * DIM * HIDDEN,
                     w2h + (long)L * DIM * HIDP, w2l + (long)L * DIM * HIDP,
                     DIM, HIDDEN, HIDP);
    }
    split_launch(out_w, owh, owl, VOCAB, DIM, DIM);

    // ---- forward pass ----
    embed_kernel<<<(SEQ * DIM + 255) / 256, 256>>>(tokens, emb, h);

    for (int L = 0; L < NL; L++) {
        rmsnorm_kernel<<<SEQ, 256>>>(h, attn_nw + L * DIM, x);
        split_launch(x, xh, xl, SEQ, DIM, DIM);

        gemm_bf3<<<ggrid(SEQ, QKVN), 256, GSMEM>>>(
            xh, xl, wqkvh + (long)L * QKVN * DIM, wqkvl + (long)L * QKVN * DIM,
            nullptr, qkv, SEQ, QKVN, DIM);

        rope_kernel<<<(SEQ * NH * (HD / 2) + 255) / 256, 256>>>(qkv);
        attn_kernel<<<dim3(SEQ / BQ, NH), 32 * BQ>>>(qkv, o);

        split_launch(o, oh, ol, SEQ, DIM, DIM);
        gemm_bf3<<<ggrid(SEQ, DIM), 256, GSMEM>>>(
            oh, ol, woh + (long)L * DIM * DIM, wol + (long)L * DIM * DIM,
            h, h, SEQ, DIM, DIM);

        rmsnorm_kernel<<<SEQ, 256>>>(h, ffn_nw + L * DIM, x);
        split_launch(x, xh, xl, SEQ, DIM, DIM);

        gemm_bf3<<<ggrid(SEQ, N13), 256, GSMEM>>>(
            xh, xl, w13h + (long)L * N13 * DIM, w13l + (long)L * N13 * DIM,
            nullptr, gg, SEQ, N13, DIM);

        silu_mul_kernel<<<(SEQ * HIDDEN + 255) / 256, 256>>>(gg, h1);
        split_launch(h1, h1h, h1l, SEQ, HIDP, HIDP);

        gemm_bf3<<<ggrid(SEQ, DIM), 256, GSMEM>>>(
            h1h, h1l, w2h + (long)L * DIM * HIDP, w2l + (long)L * DIM * HIDP,
            h, h, SEQ, DIM, HIDP);
    }

    rmsnorm_kernel<<<SEQ, 256>>>(h, norm_w, x);
    split_launch(x, xh, xl, SEQ, DIM, DIM);

    gemm_bf3<<<ggrid(SEQ, VOCAB), 256, GSMEM>>>(
        xh, xl, owh, owl, nullptr, out, SEQ, VOCAB, DIM);
}

// round 6
// speedup vs baseline: 2.1947x; 1.0429x over previous
#include <cuda_runtime.h>
#include <cuda_bf16.h>
#include <math.h>
#include <stdint.h>

#define SEQ     2048
#define DIM     768
#define NH      12
#define HD      64
#define HIDDEN  2042
#define HIDP    2048
#define N13     4096
#define QKVN    2304
#define VOCAB   32000
#define NL      4
#define THETA   10000.0f
#define ATT_SCALE 0.125f

typedef __nv_bfloat16 bf16;

// ---------------- fp32 scratch ----------------
__device__ float g_h  [SEQ * DIM];
__device__ float g_qkv[SEQ * QKVN];
__device__ float g_g  [SEQ * N13];

// ---------------- bf16 hi/lo planes (16B aligned) ----------------
__device__ __align__(16) bf16 g_wqkv_h[NL * QKVN * DIM],  g_wqkv_l[NL * QKVN * DIM];
__device__ __align__(16) bf16 g_wo_h  [NL * DIM * DIM],   g_wo_l  [NL * DIM * DIM];
__device__ __align__(16) bf16 g_w13_h [NL * N13 * DIM],   g_w13_l [NL * N13 * DIM];
__device__ __align__(16) bf16 g_w2_h  [NL * DIM * HIDP],  g_w2_l  [NL * DIM * HIDP];
__device__ __align__(16) bf16 g_ow_h  [VOCAB * DIM],      g_ow_l  [VOCAB * DIM];
__device__ __align__(16) bf16 g_xh [SEQ * DIM],  g_xl [SEQ * DIM];
__device__ __align__(16) bf16 g_oh [SEQ * DIM],  g_ol [SEQ * DIM];
__device__ __align__(16) bf16 g_h1h[SEQ * HIDP], g_h1l[SEQ * HIDP];

// ---------------- helpers ----------------
__device__ __forceinline__ void split1(float v, bf16& h, bf16& l) {
    h = __float2bfloat16(v);
    l = __float2bfloat16(v - __bfloat162float(h));
}

__global__ void split_kernel(const float* __restrict__ src,
                             bf16* __restrict__ dh, bf16* __restrict__ dl,
                             int rows, int Ks, int Kd) {
    long i = (long)blockIdx.x * blockDim.x + threadIdx.x;
    if (i >= (long)rows * Kd) return;
    int r = (int)(i / Kd), c = (int)(i - (long)r * Kd);
    float v = (c < Ks) ? src[(long)r * Ks + c] : 0.f;
    bf16 h, l; split1(v, h, l);
    dh[i] = h; dl[i] = l;
}

__global__ void embed_kernel(const int* __restrict__ tokens,
                             const float* __restrict__ emb,
                             float* __restrict__ h) {
    int i = blockIdx.x * blockDim.x + threadIdx.x;
    if (i < SEQ * DIM) {
        int s = i / DIM, d = i - s * DIM;
        h[i] = emb[(long)tokens[s] * DIM + d];
    }
}

__global__ void rmsnorm_split_kernel(const float* __restrict__ x,
                                     const float* __restrict__ w,
                                     bf16* __restrict__ yh, bf16* __restrict__ yl) {
    int row = blockIdx.x;
    const float* xr = x + (long)row * DIM;
    float ss = 0.f;
    for (int d = threadIdx.x; d < DIM; d += 256) { float t = xr[d]; ss += t * t; }
    #pragma unroll
    for (int off = 16; off; off >>= 1) ss += __shfl_xor_sync(0xffffffffu, ss, off);
    __shared__ float sred[8];
    if ((threadIdx.x & 31) == 0) sred[threadIdx.x >> 5] = ss;
    __syncthreads();
    __shared__ float s_inv;
    if (threadIdx.x == 0) {
        float tot = 0.f;
        #pragma unroll
        for (int i = 0; i < 8; i++) tot += sred[i];
        s_inv = rsqrtf(tot / (float)DIM + 1e-6f);
    }
    __syncthreads();
    float inv = s_inv;
    for (int d = threadIdx.x; d < DIM; d += 256) {
        float v = xr[d] * inv * w[d];
        bf16 hh, ll; split1(v, hh, ll);
        yh[(long)row * DIM + d] = hh;
        yl[(long)row * DIM + d] = ll;
    }
}

__global__ void rope_kernel(float* __restrict__ qkv) {
    int i = blockIdx.x * blockDim.x + threadIdx.x;
    if (i >= SEQ * NH * (HD / 2)) return;
    int p  = i % (HD / 2);
    int sh = i / (HD / 2);
    int h  = sh % NH;
    int s  = sh / NH;
    float freq = powf(THETA, -(2.0f * (float)p) / (float)HD);
    float ang  = (float)s * freq;
    float c = cosf(ang), sn = sinf(ang);
    long base = (long)s * QKVN + h * HD + 2 * p;
    float a = qkv[base], b = qkv[base + 1];
    qkv[base]     = a * c - b * sn;
    qkv[base + 1] = a * sn + b * c;
    a = qkv[base + DIM]; b = qkv[base + DIM + 1];
    qkv[base + DIM]     = a * c - b * sn;
    qkv[base + DIM + 1] = a * sn + b * c;
}

// ---------------- flash attention; output split to hi/lo ----------------
#define BQ 16
__global__ __launch_bounds__(32 * BQ)
void attn_kernel(const float* __restrict__ qkv,
                 bf16* __restrict__ ohp, bf16* __restrict__ olp) {
    int h    = blockIdx.y;
    int q0   = blockIdx.x * BQ;
    int warp = threadIdx.x >> 5;
    int lane = threadIdx.x & 31;
    int qi   = q0 + warp;

    __shared__ float Ks[64][HD + 1];
    __shared__ float Vs[64][HD + 1];
    __shared__ float Qs[BQ][HD];

    Qs[warp][lane]      = qkv[(long)qi * QKVN + h * HD + lane];
    Qs[warp][lane + 32] = qkv[(long)qi * QKVN + h * HD + lane + 32];

    float m = -INFINITY, l = 0.f, o0 = 0.f, o1 = 0.f;
    int kend = q0 + BQ;

    for (int t0 = 0; t0 < kend; t0 += 64) {
        __syncthreads();
        for (int idx = threadIdx.x; idx < 64 * HD; idx += 32 * BQ) {
            int kj = idx >> 6, d = idx & 63;
            long row = (long)(t0 + kj) * QKVN + h * HD + d;
            Ks[kj][d] = qkv[row + DIM];
            Vs[kj][d] = qkv[row + 2 * DIM];
        }
        __syncthreads();

        float s0 = 0.f, s1 = 0.f;
        #pragma unroll
        for (int d = 0; d < HD; d++) {
            float qd = Qs[warp][d];
            s0 = fmaf(qd, Ks[lane][d],      s0);
            s1 = fmaf(qd, Ks[lane + 32][d], s1);
        }
        s0 *= ATT_SCALE; s1 *= ATT_SCALE;
        if (t0 + lane      > qi) s0 = -INFINITY;
        if (t0 + lane + 32 > qi) s1 = -INFINITY;

        float mt = fmaxf(s0, s1);
        #pragma unroll
        for (int off = 16; off; off >>= 1)
            mt = fmaxf(mt, __shfl_xor_sync(0xffffffffu, mt, off));
        float mnew  = fmaxf(m, mt);
        float alpha = expf(m - mnew);
        float p0 = expf(s0 - mnew);
        float p1 = expf(s1 - mnew);
        float lsum = p0 + p1;
        #pragma unroll
        for (int off = 16; off; off >>= 1)
            lsum += __shfl_xor_sync(0xffffffffu, lsum, off);
        l = l * alpha + lsum;
        m = mnew;
        o0 *= alpha; o1 *= alpha;

        #pragma unroll
        for (int j = 0; j < 32; j++) {
            float pa = __shfl_sync(0xffffffffu, p0, j);
            float pb = __shfl_sync(0xffffffffu, p1, j);
            o0 = fmaf(pa, Vs[j][lane],           o0);
            o0 = fmaf(pb, Vs[j + 32][lane],      o0);
            o1 = fmaf(pa, Vs[j][lane + 32],      o1);
            o1 = fmaf(pb, Vs[j + 32][lane + 32], o1);
        }
    }
    float inv = 1.f / l;
    float v0 = o0 * inv, v1 = o1 * inv;
    bf16 hh, ll;
    long base = (long)qi * DIM + h * HD;
    split1(v0, hh, ll); ohp[base + lane]      = hh; olp[base + lane]      = ll;
    split1(v1, hh, ll); ohp[base + lane + 32] = hh; olp[base + lane + 32] = ll;
}

__global__ void silu_split_kernel(const float* __restrict__ gg,
                                  bf16* __restrict__ h1h, bf16* __restrict__ h1l) {
    int i = blockIdx.x * blockDim.x + threadIdx.x;
    if (i < SEQ * HIDDEN) {
        int s = i / HIDDEN, j = i - s * HIDDEN;
        float a = gg[(long)s * N13 + j];
        float b = gg[(long)s * N13 + HIDP + j];
        float sl = a / (1.f + expf(-a));
        float v = sl * b;
        bf16 hh, ll; split1(v, hh, ll);
        h1h[(long)s * HIDP + j] = hh;
        h1l[(long)s * HIDP + j] = ll;
    }
}

// ================= bf16x3 mma.sync GEMM with ldmatrix fragments =================
// C[M,N] = A@B^T (+res). M,N mult of 128, K mult of 32. 128x128x32 CTA tile,
// 256 thr (8 warps, warp tile 64x32), cp.async double buffer.
// Smem plane: 128 rows x 20 u32 (16 data u32 = 32 bf16 k, 4 pad). 4 planes/stage.
#define PL_U32 2560
#define ST_U32 (4 * PL_U32)
#define GSMEM  (2 * ST_U32 * 4)   // 81920 B

__device__ __forceinline__ void mma_bf16(float* d, const uint32_t* a, const uint32_t* b) {
    asm volatile(
        "mma.sync.aligned.m16n8k16.row.col.f32.bf16.bf16.f32 "
        "{%0,%1,%2,%3}, {%4,%5,%6,%7}, {%8,%9}, {%0,%1,%2,%3};"
        : "+f"(d[0]), "+f"(d[1]), "+f"(d[2]), "+f"(d[3])
        : "r"(a[0]), "r"(a[1]), "r"(a[2]), "r"(a[3]), "r"(b[0]), "r"(b[1]));
}
__device__ __forceinline__ void ldmx4(uint32_t* r, uint32_t addr) {
    asm volatile("ldmatrix.sync.aligned.m8n8.x4.shared.b16 {%0,%1,%2,%3}, [%4];"
                 : "=r"(r[0]), "=r"(r[1]), "=r"(r[2]), "=r"(r[3]) : "r"(addr));
}
__device__ __forceinline__ void cpa16(uint32_t dst, const void* src) {
    asm volatile("cp.async.cg.shared.global [%0], [%1], 16;" :: "r"(dst), "l"(src));
}

__global__ __launch_bounds__(256, 2)
void gemm_bf3(const bf16* __restrict__ Ah, const bf16* __restrict__ Al,
              const bf16* __restrict__ Bh, const bf16* __restrict__ Bl,
              const float* __restrict__ res, float* __restrict__ C,
              int M, int N, int K) {
    extern __shared__ uint32_t sm[];
    int bm = blockIdx.y * 128;
    int bn = blockIdx.x * 128;
    int tid  = threadIdx.x;
    int warp = tid >> 5, lane = tid & 31;
    int wm = (warp >> 2) * 64;
    int wn = (warp & 3) * 32;
    int g  = lane >> 2, tg = lane & 3;
    int rr = lane & 7, q = lane >> 3;

    uint32_t sbase = (uint32_t)__cvta_generic_to_shared(sm);

    // per-lane ldmatrix base byte offsets within a plane
    // A 16x16 tile: q&1 -> +8 rows, q>>1 -> +4 u32 (k+8)
    uint32_t aoff = (uint32_t)(((wm + rr + (q & 1) * 8) * 20 + (q >> 1) * 4) * 4);
    // B pair of n8 tiles: q>>1 -> +8 n-rows, q&1 -> +4 u32 (k+8)
    uint32_t boff = (uint32_t)(((wn + rr + (q >> 1) * 8) * 20 + (q & 1) * 4) * 4);

    // loader: per plane, 2 chunks of 16B per thread (512 chunks/plane)
    int c0 = tid * 2, c1 = c0 + 1;
    int lr0 = c0 >> 2, kc0 = c0 & 3;
    int lr1 = c1 >> 2, kc1 = c1 & 3;
    uint32_t so0 = (uint32_t)((lr0 * 20 + kc0 * 4) * 4);
    uint32_t so1 = (uint32_t)((lr1 * 20 + kc1 * 4) * 4);

    float acc[4][4][4];
    #pragma unroll
    for (int mi = 0; mi < 4; mi++)
        #pragma unroll
        for (int ni = 0; ni < 4; ni++)
            #pragma unroll
            for (int r = 0; r < 4; r++) acc[mi][ni][r] = 0.f;

    const bf16* pl[4] = { Ah, Al, Bh, Bl };
    long rA0 = (long)(bm + lr0) * K, rA1 = (long)(bm + lr1) * K;
    long rB0 = (long)(bn + lr0) * K, rB1 = (long)(bn + lr1) * K;

    int KT = K / 32;

    auto fill = [&](int s, int kk0) {
        uint32_t st = sbase + (uint32_t)s * ST_U32 * 4;
        #pragma unroll
        for (int p = 0; p < 4; p++) {
            long ro0 = (p < 2) ? rA0 : rB0;
            long ro1 = (p < 2) ? rA1 : rB1;
            uint32_t d = st + (uint32_t)p * PL_U32 * 4;
            cpa16(d + so0, pl[p] + ro0 + kk0 + kc0 * 8);
            cpa16(d + so1, pl[p] + ro1 + kk0 + kc1 * 8);
        }
        asm volatile("cp.async.commit_group;");
    };

    fill(0, 0);

    for (int kt = 0; kt < KT; kt++) {
        if (kt + 1 < KT) {
            fill((kt + 1) & 1, (kt + 1) * 32);
            asm volatile("cp.async.wait_group 1;");
        } else {
            asm volatile("cp.async.wait_group 0;");
        }
        __syncthreads();

        uint32_t st  = sbase + (uint32_t)(kt & 1) * ST_U32 * 4;
        uint32_t pAH = st;
        uint32_t pAL = st + PL_U32 * 4;
        uint32_t pBH = st + 2 * PL_U32 * 4;
        uint32_t pBL = st + 3 * PL_U32 * 4;

        #pragma unroll
        for (int ks = 0; ks < 2; ks++) {
            uint32_t ko = (uint32_t)ks * 32;   // 8 u32 per k16 step

            uint32_t afH[4][4], bfH[4][2], bfX[4][2];
            #pragma unroll
            for (int mi = 0; mi < 4; mi++)
                ldmx4(afH[mi], pAH + aoff + mi * 1280 + ko);
            #pragma unroll
            for (int n2 = 0; n2 < 2; n2++) {
                uint32_t t[4];
                ldmx4(t, pBH + boff + n2 * 1280 + ko);
                bfH[2 * n2][0] = t[0]; bfH[2 * n2][1] = t[1];
                bfH[2 * n2 + 1][0] = t[2]; bfH[2 * n2 + 1][1] = t[3];
            }
            #pragma unroll
            for (int mi = 0; mi < 4; mi++)
                #pragma unroll
                for (int ni = 0; ni < 4; ni++)
                    mma_bf16(acc[mi][ni], afH[mi], bfH[ni]);

            // hiA * loB
            #pragma unroll
            for (int n2 = 0; n2 < 2; n2++) {
                uint32_t t[4];
                ldmx4(t, pBL + boff + n2 * 1280 + ko);
                bfX[2 * n2][0] = t[0]; bfX[2 * n2][1] = t[1];
                bfX[2 * n2 + 1][0] = t[2]; bfX[2 * n2 + 1][1] = t[3];
            }
            #pragma unroll
            for (int mi = 0; mi < 4; mi++)
                #pragma unroll
                for (int ni = 0; ni < 4; ni++)
                    mma_bf16(acc[mi][ni], afH[mi], bfX[ni]);

            // loA * hiB (reuse afH storage for afL)
            #pragma unroll
            for (int mi = 0; mi < 4; mi++)
                ldmx4(afH[mi], pAL + aoff + mi * 1280 + ko);
            #pragma unroll
            for (int mi = 0; mi < 4; mi++)
                #pragma unroll
                for (int ni = 0; ni < 4; ni++)
                    mma_bf16(acc[mi][ni], afH[mi], bfH[ni]);
        }
        __syncthreads();
    }

    // epilogue
    #pragma unroll
    for (int mi = 0; mi < 4; mi++) {
        int row0 = bm + wm + mi * 16 + g;
        #pragma unroll
        for (int ni = 0; ni < 4; ni++) {
            int col = bn + wn + ni * 8 + tg * 2;
            #pragma unroll
            for (int half = 0; half < 2; half++) {
                int row = row0 + half * 8;
                long idx = (long)row * N + col;
                float v0 = acc[mi][ni][half * 2 + 0];
                float v1 = acc[mi][ni][half * 2 + 1];
                if (res) { v0 += res[idx]; v1 += res[idx + 1]; }
                C[idx]     = v0;
                C[idx + 1] = v1;
            }
        }
    }
}

// ---------------- host launcher ----------------
static inline dim3 ggrid(int M, int N) { return dim3(N / 128, M / 128); }

static inline void split_launch(const float* src, bf16* dh, bf16* dl,
                                int rows, int Ks, int Kd) {
    long n = (long)rows * Kd;
    split_kernel<<<(unsigned)((n + 255) / 256), 256>>>(src, dh, dl, rows, Ks, Kd);
}

extern "C" void kernel_launch(void* const* d_in, const int* in_sizes, int n_in,
                              void* d_out, int out_size) {
    const int*   tokens   = (const int*)  d_in[0];
    const float* emb      = (const float*)d_in[1];
    const float* wq       = (const float*)d_in[2];
    const float* wk       = (const float*)d_in[3];
    const float* wv       = (const float*)d_in[4];
    const float* wo       = (const float*)d_in[5];
    const float* w1       = (const float*)d_in[6];
    const float* w2       = (const float*)d_in[7];
    const float* w3       = (const float*)d_in[8];
    const float* attn_nw  = (const float*)d_in[9];
    const float* ffn_nw   = (const float*)d_in[10];
    const float* norm_w   = (const float*)d_in[11];
    const float* out_w    = (const float*)d_in[12];
    float* out = (float*)d_out;

    float *h, *qkv, *gg;
    cudaGetSymbolAddress((void**)&h,   g_h);
    cudaGetSymbolAddress((void**)&qkv, g_qkv);
    cudaGetSymbolAddress((void**)&gg,  g_g);

    bf16 *wqkvh, *wqkvl, *woh, *wol, *w13h, *w13l, *w2h, *w2l, *owh, *owl;
    bf16 *xh, *xl, *oh, *ol, *h1h, *h1l;
    cudaGetSymbolAddress((void**)&wqkvh, g_wqkv_h); cudaGetSymbolAddress((void**)&wqkvl, g_wqkv_l);
    cudaGetSymbolAddress((void**)&woh,   g_wo_h);   cudaGetSymbolAddress((void**)&wol,   g_wo_l);
    cudaGetSymbolAddress((void**)&w13h,  g_w13_h);  cudaGetSymbolAddress((void**)&w13l,  g_w13_l);
    cudaGetSymbolAddress((void**)&w2h,   g_w2_h);   cudaGetSymbolAddress((void**)&w2l,   g_w2_l);
    cudaGetSymbolAddress((void**)&owh,   g_ow_h);   cudaGetSymbolAddress((void**)&owl,   g_ow_l);
    cudaGetSymbolAddress((void**)&xh,  g_xh);  cudaGetSymbolAddress((void**)&xl,  g_xl);
    cudaGetSymbolAddress((void**)&oh,  g_oh);  cudaGetSymbolAddress((void**)&ol,  g_ol);
    cudaGetSymbolAddress((void**)&h1h, g_h1h); cudaGetSymbolAddress((void**)&h1l, g_h1l);

    cudaFuncSetAttribute(gemm_bf3, cudaFuncAttributeMaxDynamicSharedMemorySize, GSMEM);

    // ---- weight conversion ----
    for (int L = 0; L < NL; L++) {
        long wOff = (long)L * DIM * DIM;
        split_launch(wq + wOff, wqkvh + ((long)L * QKVN + 0)      * DIM,
                                wqkvl + ((long)L * QKVN + 0)      * DIM, DIM, DIM, DIM);
        split_launch(wk + wOff, wqkvh + ((long)L * QKVN + DIM)    * DIM,
                                wqkvl + ((long)L * QKVN + DIM)    * DIM, DIM, DIM, DIM);
        split_launch(wv + wOff, wqkvh + ((long)L * QKVN + 2*DIM)  * DIM,
                                wqkvl + ((long)L * QKVN + 2*DIM)  * DIM, DIM, DIM, DIM);
        split_launch(wo + wOff, woh + wOff, wol + wOff, DIM, DIM, DIM);
        long w1Off = (long)L * HIDDEN * DIM;
        split_launch(w1 + w1Off, w13h + (long)L * N13 * DIM,
                                 w13l + (long)L * N13 * DIM, HIDDEN, DIM, DIM);
        split_launch(w3 + w1Off, w13h + ((long)L * N13 + HIDP) * DIM,
                                 w13l + ((long)L * N13 + HIDP) * DIM, HIDDEN, DIM, DIM);
        split_launch(w2 + (long)L * DIM * HIDDEN,
                     w2h + (long)L * DIM * HIDP, w2l + (long)L * DIM * HIDP,
                     DIM, HIDDEN, HIDP);
    }
    split_launch(out_w, owh, owl, VOCAB, DIM, DIM);

    // ---- forward ----
    embed_kernel<<<(SEQ * DIM + 255) / 256, 256>>>(tokens, emb, h);

    for (int L = 0; L < NL; L++) {
        rmsnorm_split_kernel<<<SEQ, 256>>>(h, attn_nw + L * DIM, xh, xl);

        gemm_bf3<<<ggrid(SEQ, QKVN), 256, GSMEM>>>(
            xh, xl, wqkvh + (long)L * QKVN * DIM, wqkvl + (long)L * QKVN * DIM,
            nullptr, qkv, SEQ, QKVN, DIM);

        rope_kernel<<<(SEQ * NH * (HD / 2) + 255) / 256, 256>>>(qkv);
        attn_kernel<<<dim3(SEQ / BQ, NH), 32 * BQ>>>(qkv, oh, ol);

        gemm_bf3<<<ggrid(SEQ, DIM), 256, GSMEM>>>(
            oh, ol, woh + (long)L * DIM * DIM, wol + (long)L * DIM * DIM,
            h, h, SEQ, DIM, DIM);

        rmsnorm_split_kernel<<<SEQ, 256>>>(h, ffn_nw + L * DIM, xh, xl);

        gemm_bf3<<<ggrid(SEQ, N13), 256, GSMEM>>>(
            xh, xl, w13h + (long)L * N13 * DIM, w13l + (long)L * N13 * DIM,
            nullptr, gg, SEQ, N13, DIM);

        silu_split_kernel<<<(SEQ * HIDDEN + 255) / 256, 256>>>(gg, h1h, h1l);

        gemm_bf3<<<ggrid(SEQ, DIM), 256, GSMEM>>>(
            h1h, h1l, w2h + (long)L * DIM * HIDP, w2l + (long)L * DIM * HIDP,
            h, h, SEQ, DIM, HIDP);
    }

    rmsnorm_split_kernel<<<SEQ, 256>>>(h, norm_w, xh, xl);

    gemm_bf3<<<ggrid(SEQ, VOCAB), 256, GSMEM>>>(
        xh, xl, owh, owl, nullptr, out, SEQ, VOCAB, DIM);
}

// round 7
// speedup vs baseline: 2.5014x; 1.1398x over previous
#include <cuda_runtime.h>
#include <cuda_bf16.h>
#include <math.h>
#include <stdint.h>

#define SEQ     2048
#define DIM     768
#define NH      12
#define HD      64
#define HIDDEN  2042
#define HIDP    2048
#define N13     4096
#define QKVN    2304
#define VOCAB   32000
#define NL      4
#define THETA   10000.0f
#define ATT_SCALE 0.125f

typedef __nv_bfloat16 bf16;
typedef __nv_bfloat162 bf162;

// ---------------- fp32 scratch ----------------
__device__ float g_h  [SEQ * DIM];
__device__ float g_qkv[SEQ * QKVN];
__device__ float g_g  [SEQ * N13];

// ---------------- bf16 hi/lo planes (16B aligned) ----------------
__device__ __align__(16) bf16 g_wqkv_h[NL * QKVN * DIM],  g_wqkv_l[NL * QKVN * DIM];
__device__ __align__(16) bf16 g_wo_h  [NL * DIM * DIM],   g_wo_l  [NL * DIM * DIM];
__device__ __align__(16) bf16 g_w13_h [NL * N13 * DIM],   g_w13_l [NL * N13 * DIM];
__device__ __align__(16) bf16 g_w2_h  [NL * DIM * HIDP],  g_w2_l  [NL * DIM * HIDP];
__device__ __align__(16) bf16 g_ow_h  [VOCAB * DIM],      g_ow_l  [VOCAB * DIM];
__device__ __align__(16) bf16 g_xh [SEQ * DIM],  g_xl [SEQ * DIM];
__device__ __align__(16) bf16 g_oh [SEQ * DIM],  g_ol [SEQ * DIM];
__device__ __align__(16) bf16 g_h1h[SEQ * HIDP], g_h1l[SEQ * HIDP];

// ---------------- helpers ----------------
__device__ __forceinline__ void split1(float v, bf16& h, bf16& l) {
    h = __float2bfloat16(v);
    l = __float2bfloat16(v - __bfloat162float(h));
}

// vectorized split: Ks == Kd, total elems % 4 == 0
__global__ void split4_kernel(const float4* __restrict__ src,
                              bf162* __restrict__ dh, bf162* __restrict__ dl,
                              long n4) {
    long stride = (long)gridDim.x * blockDim.x;
    for (long i = (long)blockIdx.x * blockDim.x + threadIdx.x; i < n4; i += stride) {
        float4 v = src[i];
        bf16 h0, l0, h1, l1, h2, l2, h3, l3;
        split1(v.x, h0, l0); split1(v.y, h1, l1);
        split1(v.z, h2, l2); split1(v.w, h3, l3);
        dh[i * 2]     = __halves2bfloat162(h0, h1);
        dh[i * 2 + 1] = __halves2bfloat162(h2, h3);
        dl[i * 2]     = __halves2bfloat162(l0, l1);
        dl[i * 2 + 1] = __halves2bfloat162(l2, l3);
    }
}

// split for w2: rows x Ks=2042 -> rows x Kd=2048, float2 granularity
__global__ void split2_pad_kernel(const float* __restrict__ src,
                                  bf162* __restrict__ dh, bf162* __restrict__ dl,
                                  int rows, int Ks, int Kd) {
    long n2 = (long)rows * (Kd / 2);
    long stride = (long)gridDim.x * blockDim.x;
    for (long i = (long)blockIdx.x * blockDim.x + threadIdx.x; i < n2; i += stride) {
        int r  = (int)(i / (Kd / 2));
        int c2 = (int)(i - (long)r * (Kd / 2));
        float2 v = make_float2(0.f, 0.f);
        if (c2 * 2 + 1 < Ks)
            v = *reinterpret_cast<const float2*>(src + (long)r * Ks + c2 * 2);
        bf16 h0, l0, h1, l1;
        split1(v.x, h0, l0); split1(v.y, h1, l1);
        dh[i] = __halves2bfloat162(h0, h1);
        dl[i] = __halves2bfloat162(l0, l1);
    }
}

__global__ void embed_kernel(const int* __restrict__ tokens,
                             const float* __restrict__ emb,
                             float* __restrict__ h) {
    int i = blockIdx.x * blockDim.x + threadIdx.x;
    if (i < SEQ * DIM) {
        int s = i / DIM, d = i - s * DIM;
        h[i] = emb[(long)tokens[s] * DIM + d];
    }
}

__global__ void rmsnorm_split_kernel(const float* __restrict__ x,
                                     const float* __restrict__ w,
                                     bf16* __restrict__ yh, bf16* __restrict__ yl) {
    int row = blockIdx.x;
    const float* xr = x + (long)row * DIM;
    float ss = 0.f;
    for (int d = threadIdx.x; d < DIM; d += 256) { float t = xr[d]; ss += t * t; }
    #pragma unroll
    for (int off = 16; off; off >>= 1) ss += __shfl_xor_sync(0xffffffffu, ss, off);
    __shared__ float sred[8];
    if ((threadIdx.x & 31) == 0) sred[threadIdx.x >> 5] = ss;
    __syncthreads();
    __shared__ float s_inv;
    if (threadIdx.x == 0) {
        float tot = 0.f;
        #pragma unroll
        for (int i = 0; i < 8; i++) tot += sred[i];
        s_inv = rsqrtf(tot / (float)DIM + 1e-6f);
    }
    __syncthreads();
    float inv = s_inv;
    for (int d = threadIdx.x; d < DIM; d += 256) {
        float v = xr[d] * inv * w[d];
        bf16 hh, ll; split1(v, hh, ll);
        yh[(long)row * DIM + d] = hh;
        yl[(long)row * DIM + d] = ll;
    }
}

__global__ void rope_kernel(float* __restrict__ qkv) {
    int i = blockIdx.x * blockDim.x + threadIdx.x;
    if (i >= SEQ * NH * (HD / 2)) return;
    int p  = i % (HD / 2);
    int sh = i / (HD / 2);
    int h  = sh % NH;
    int s  = sh / NH;
    float freq = powf(THETA, -(2.0f * (float)p) / (float)HD);
    float ang  = (float)s * freq;
    float c = cosf(ang), sn = sinf(ang);
    long base = (long)s * QKVN + h * HD + 2 * p;
    float a = qkv[base], b = qkv[base + 1];
    qkv[base]     = a * c - b * sn;
    qkv[base + 1] = a * sn + b * c;
    a = qkv[base + DIM]; b = qkv[base + DIM + 1];
    qkv[base + DIM]     = a * c - b * sn;
    qkv[base + DIM + 1] = a * sn + b * c;
}

// ---------------- flash attention; output split to hi/lo ----------------
#define BQ 16
__global__ __launch_bounds__(32 * BQ)
void attn_kernel(const float* __restrict__ qkv,
                 bf16* __restrict__ ohp, bf16* __restrict__ olp) {
    int h    = blockIdx.y;
    int q0   = blockIdx.x * BQ;
    int warp = threadIdx.x >> 5;
    int lane = threadIdx.x & 31;
    int qi   = q0 + warp;

    __shared__ float Ks[64][HD + 1];
    __shared__ float Vs[64][HD + 1];
    __shared__ float Qs[BQ][HD];

    Qs[warp][lane]      = qkv[(long)qi * QKVN + h * HD + lane];
    Qs[warp][lane + 32] = qkv[(long)qi * QKVN + h * HD + lane + 32];

    float m = -INFINITY, l = 0.f, o0 = 0.f, o1 = 0.f;
    int kend = q0 + BQ;

    for (int t0 = 0; t0 < kend; t0 += 64) {
        __syncthreads();
        for (int idx = threadIdx.x; idx < 64 * HD; idx += 32 * BQ) {
            int kj = idx >> 6, d = idx & 63;
            long row = (long)(t0 + kj) * QKVN + h * HD + d;
            Ks[kj][d] = qkv[row + DIM];
            Vs[kj][d] = qkv[row + 2 * DIM];
        }
        __syncthreads();

        float s0 = 0.f, s1 = 0.f;
        #pragma unroll
        for (int d = 0; d < HD; d++) {
            float qd = Qs[warp][d];
            s0 = fmaf(qd, Ks[lane][d],      s0);
            s1 = fmaf(qd, Ks[lane + 32][d], s1);
        }
        s0 *= ATT_SCALE; s1 *= ATT_SCALE;
        if (t0 + lane      > qi) s0 = -INFINITY;
        if (t0 + lane + 32 > qi) s1 = -INFINITY;

        float mt = fmaxf(s0, s1);
        #pragma unroll
        for (int off = 16; off; off >>= 1)
            mt = fmaxf(mt, __shfl_xor_sync(0xffffffffu, mt, off));
        float mnew  = fmaxf(m, mt);
        float alpha = expf(m - mnew);
        float p0 = expf(s0 - mnew);
        float p1 = expf(s1 - mnew);
        float lsum = p0 + p1;
        #pragma unroll
        for (int off = 16; off; off >>= 1)
            lsum += __shfl_xor_sync(0xffffffffu, lsum, off);
        l = l * alpha + lsum;
        m = mnew;
        o0 *= alpha; o1 *= alpha;

        #pragma unroll
        for (int j = 0; j < 32; j++) {
            float pa = __shfl_sync(0xffffffffu, p0, j);
            float pb = __shfl_sync(0xffffffffu, p1, j);
            o0 = fmaf(pa, Vs[j][lane],           o0);
            o0 = fmaf(pb, Vs[j + 32][lane],      o0);
            o1 = fmaf(pa, Vs[j][lane + 32],      o1);
            o1 = fmaf(pb, Vs[j + 32][lane + 32], o1);
        }
    }
    float inv = 1.f / l;
    float v0 = o0 * inv, v1 = o1 * inv;
    bf16 hh, ll;
    long base = (long)qi * DIM + h * HD;
    split1(v0, hh, ll); ohp[base + lane]      = hh; olp[base + lane]      = ll;
    split1(v1, hh, ll); ohp[base + lane + 32] = hh; olp[base + lane + 32] = ll;
}

__global__ void silu_split_kernel(const float* __restrict__ gg,
                                  bf16* __restrict__ h1h, bf16* __restrict__ h1l) {
    int i = blockIdx.x * blockDim.x + threadIdx.x;
    if (i < SEQ * HIDDEN) {
        int s = i / HIDDEN, j = i - s * HIDDEN;
        float a = gg[(long)s * N13 + j];
        float b = gg[(long)s * N13 + HIDP + j];
        float sl = a / (1.f + expf(-a));
        float v = sl * b;
        bf16 hh, ll; split1(v, hh, ll);
        h1h[(long)s * HIDP + j] = hh;
        h1l[(long)s * HIDP + j] = ll;
    }
}

// ================= templated bf16x3 mma.sync GEMM, swizzled smem =================
// C[M,N] = A@B^T (+res). BM==BN tiles, K%32==0. Smem plane: BM rows x 64B (k32),
// chunk swizzle: byte = row*64 + ((ch ^ ((row>>1)&3))<<4). Double buffered.
__device__ __forceinline__ void mma_bf16(float* d, const uint32_t* a, const uint32_t* b) {
    asm volatile(
        "mma.sync.aligned.m16n8k16.row.col.f32.bf16.bf16.f32 "
        "{%0,%1,%2,%3}, {%4,%5,%6,%7}, {%8,%9}, {%0,%1,%2,%3};"
        : "+f"(d[0]), "+f"(d[1]), "+f"(d[2]), "+f"(d[3])
        : "r"(a[0]), "r"(a[1]), "r"(a[2]), "r"(a[3]), "r"(b[0]), "r"(b[1]));
}
__device__ __forceinline__ void ldmx4(uint32_t* r, uint32_t addr) {
    asm volatile("ldmatrix.sync.aligned.m8n8.x4.shared.b16 {%0,%1,%2,%3}, [%4];"
                 : "=r"(r[0]), "=r"(r[1]), "=r"(r[2]), "=r"(r[3]) : "r"(addr));
}
__device__ __forceinline__ void cpa16(uint32_t dst, const void* src) {
    asm volatile("cp.async.cg.shared.global [%0], [%1], 16;" :: "r"(dst), "l"(src));
}

template<int BM, int WM, int WN, int THREADS, int MAXB>
__global__ __launch_bounds__(THREADS, MAXB)
void gemm_bf3(const bf16* __restrict__ Ah, const bf16* __restrict__ Al,
              const bf16* __restrict__ Bh, const bf16* __restrict__ Bl,
              const float* __restrict__ res, float* __restrict__ C,
              int M, int N, int K) {
    const int BN = BM;
    const int WARPS_N = BN / WN;
    const int MT = WM / 16;
    const int NT = WN / 8;
    const int PB = BM * 64;          // plane bytes
    const int SB = 4 * PB;           // stage bytes
    const int CHUNKS = 4 * BM * 4;   // 16*BM, chunks per stage
    const int CPT = CHUNKS / THREADS;

    extern __shared__ char smc[];
    uint32_t sbase = (uint32_t)__cvta_generic_to_shared(smc);

    int bm = blockIdx.y * BM;
    int bn = blockIdx.x * BN;
    int tid  = threadIdx.x;
    int warp = tid >> 5, lane = tid & 31;
    int wm = (warp / WARPS_N) * WM;
    int wn = (warp % WARPS_N) * WN;
    int g  = lane >> 2, tg = lane & 3;
    int rr = lane & 7, q = lane >> 3;

    // ldmatrix per-lane bases (byte offsets within a plane)
    int aRowL = wm + rr + 8 * (q & 1);
    int bRowL = wn + rr + 8 * (q >> 1);
    uint32_t aRowOff = (uint32_t)aRowL * 64;
    uint32_t bRowOff = (uint32_t)bRowL * 64;
    uint32_t swA = (uint32_t)((aRowL >> 1) & 3);
    uint32_t swB = (uint32_t)((bRowL >> 1) & 3);
    uint32_t cA[2], cB[2];
    #pragma unroll
    for (int ks = 0; ks < 2; ks++) {
        cA[ks] = ((uint32_t)(2 * ks + (q >> 1)) ^ swA) << 4;
        cB[ks] = ((uint32_t)(2 * ks + (q & 1))  ^ swB) << 4;
    }

    // loader precompute: CPT chunks per thread
    const bf16* pl[4] = { Ah, Al, Bh, Bl };
    uint32_t dstoff[CPT];
    const bf16* srcb[CPT];
    #pragma unroll
    for (int t = 0; t < CPT; t++) {
        int cid = tid + t * THREADS;
        int p   = cid / (BM * 4);
        int rem = cid - p * (BM * 4);
        int row = rem >> 2, ch = rem & 3;
        dstoff[t] = (uint32_t)p * PB + (uint32_t)row * 64
                  + (((uint32_t)ch ^ (((uint32_t)row >> 1) & 3)) << 4);
        int rowG = ((p < 2) ? bm : bn) + row;
        srcb[t] = pl[p] + (long)rowG * K + ch * 8;
    }

    float acc[MT][NT][4];
    #pragma unroll
    for (int mi = 0; mi < MT; mi++)
        #pragma unroll
        for (int ni = 0; ni < NT; ni++)
            #pragma unroll
            for (int r = 0; r < 4; r++) acc[mi][ni][r] = 0.f;

    int KT = K / 32;

    auto fill = [&](int s, int kk0) {
        uint32_t st = sbase + (uint32_t)s * SB;
        #pragma unroll
        for (int t = 0; t < CPT; t++)
            cpa16(st + dstoff[t], srcb[t] + kk0);
        asm volatile("cp.async.commit_group;");
    };

    fill(0, 0);

    for (int kt = 0; kt < KT; kt++) {
        if (kt + 1 < KT) {
            fill((kt + 1) & 1, (kt + 1) * 32);
            asm volatile("cp.async.wait_group 1;");
        } else {
            asm volatile("cp.async.wait_group 0;");
        }
        __syncthreads();

        uint32_t st  = sbase + (uint32_t)(kt & 1) * SB;
        uint32_t pAH = st;
        uint32_t pAL = st + PB;
        uint32_t pBH = st + 2 * PB;
        uint32_t pBL = st + 3 * PB;

        #pragma unroll
        for (int ks = 0; ks < 2; ks++) {
            uint32_t afH[MT][4], bfH[NT][2], bfX[NT][2];
            #pragma unroll
            for (int mi = 0; mi < MT; mi++)
                ldmx4(afH[mi], pAH + aRowOff + (uint32_t)mi * 1024 + cA[ks]);
            #pragma unroll
            for (int n2 = 0; n2 < NT / 2; n2++) {
                uint32_t t[4];
                ldmx4(t, pBH + bRowOff + (uint32_t)n2 * 1024 + cB[ks]);
                bfH[2 * n2][0] = t[0]; bfH[2 * n2][1] = t[1];
                bfH[2 * n2 + 1][0] = t[2]; bfH[2 * n2 + 1][1] = t[3];
            }
            #pragma unroll
            for (int mi = 0; mi < MT; mi++)
                #pragma unroll
                for (int ni = 0; ni < NT; ni++)
                    mma_bf16(acc[mi][ni], afH[mi], bfH[ni]);

            #pragma unroll
            for (int n2 = 0; n2 < NT / 2; n2++) {
                uint32_t t[4];
                ldmx4(t, pBL + bRowOff + (uint32_t)n2 * 1024 + cB[ks]);
                bfX[2 * n2][0] = t[0]; bfX[2 * n2][1] = t[1];
                bfX[2 * n2 + 1][0] = t[2]; bfX[2 * n2 + 1][1] = t[3];
            }
            #pragma unroll
            for (int mi = 0; mi < MT; mi++)
                #pragma unroll
                for (int ni = 0; ni < NT; ni++)
                    mma_bf16(acc[mi][ni], afH[mi], bfX[ni]);

            #pragma unroll
            for (int mi = 0; mi < MT; mi++)
                ldmx4(afH[mi], pAL + aRowOff + (uint32_t)mi * 1024 + cA[ks]);
            #pragma unroll
            for (int mi = 0; mi < MT; mi++)
                #pragma unroll
                for (int ni = 0; ni < NT; ni++)
                    mma_bf16(acc[mi][ni], afH[mi], bfH[ni]);
        }
        __syncthreads();
    }

    #pragma unroll
    for (int mi = 0; mi < MT; mi++) {
        int row0 = bm + wm + mi * 16 + g;
        #pragma unroll
        for (int ni = 0; ni < NT; ni++) {
            int col = bn + wn + ni * 8 + tg * 2;
            #pragma unroll
            for (int half = 0; half < 2; half++) {
                int row = row0 + half * 8;
                long idx = (long)row * N + col;
                float v0 = acc[mi][ni][half * 2 + 0];
                float v1 = acc[mi][ni][half * 2 + 1];
                if (res) { v0 += res[idx]; v1 += res[idx + 1]; }
                C[idx]     = v0;
                C[idx + 1] = v1;
            }
        }
    }
}

// instantiations
#define GEMM_BIG   gemm_bf3<128, 64, 32, 256, 2>
#define GEMM_SMALL gemm_bf3< 64, 32, 32, 128, 5>
#define SMEM_BIG   (2 * 4 * 128 * 64)   // 65536
#define SMEM_SMALL (2 * 4 * 64 * 64)    // 32768

// ---------------- host launcher ----------------
static inline void split4_launch(const float* src, bf16* dh, bf16* dl, long n) {
    long n4 = n / 4;
    int blocks = (int)((n4 + 255) / 256);
    if (blocks > 4096) blocks = 4096;
    split4_kernel<<<blocks, 256>>>((const float4*)src, (bf162*)dh, (bf162*)dl, n4);
}

extern "C" void kernel_launch(void* const* d_in, const int* in_sizes, int n_in,
                              void* d_out, int out_size) {
    const int*   tokens   = (const int*)  d_in[0];
    const float* emb      = (const float*)d_in[1];
    const float* wq       = (const float*)d_in[2];
    const float* wk       = (const float*)d_in[3];
    const float* wv       = (const float*)d_in[4];
    const float* wo       = (const float*)d_in[5];
    const float* w1       = (const float*)d_in[6];
    const float* w2       = (const float*)d_in[7];
    const float* w3       = (const float*)d_in[8];
    const float* attn_nw  = (const float*)d_in[9];
    const float* ffn_nw   = (const float*)d_in[10];
    const float* norm_w   = (const float*)d_in[11];
    const float* out_w    = (const float*)d_in[12];
    float* out = (float*)d_out;

    float *h, *qkv, *gg;
    cudaGetSymbolAddress((void**)&h,   g_h);
    cudaGetSymbolAddress((void**)&qkv, g_qkv);
    cudaGetSymbolAddress((void**)&gg,  g_g);

    bf16 *wqkvh, *wqkvl, *woh, *wol, *w13h, *w13l, *w2h, *w2l, *owh, *owl;
    bf16 *xh, *xl, *oh, *ol, *h1h, *h1l;
    cudaGetSymbolAddress((void**)&wqkvh, g_wqkv_h); cudaGetSymbolAddress((void**)&wqkvl, g_wqkv_l);
    cudaGetSymbolAddress((void**)&woh,   g_wo_h);   cudaGetSymbolAddress((void**)&wol,   g_wo_l);
    cudaGetSymbolAddress((void**)&w13h,  g_w13_h);  cudaGetSymbolAddress((void**)&w13l,  g_w13_l);
    cudaGetSymbolAddress((void**)&w2h,   g_w2_h);   cudaGetSymbolAddress((void**)&w2l,   g_w2_l);
    cudaGetSymbolAddress((void**)&owh,   g_ow_h);   cudaGetSymbolAddress((void**)&owl,   g_ow_l);
    cudaGetSymbolAddress((void**)&xh,  g_xh);  cudaGetSymbolAddress((void**)&xl,  g_xl);
    cudaGetSymbolAddress((void**)&oh,  g_oh);  cudaGetSymbolAddress((void**)&ol,  g_ol);
    cudaGetSymbolAddress((void**)&h1h, g_h1h); cudaGetSymbolAddress((void**)&h1l, g_h1l);

    cudaFuncSetAttribute(GEMM_BIG,   cudaFuncAttributeMaxDynamicSharedMemorySize, SMEM_BIG);
    cudaFuncSetAttribute(GEMM_SMALL, cudaFuncAttributeMaxDynamicSharedMemorySize, SMEM_SMALL);

    // ---- weight conversion (vectorized) ----
    for (int L = 0; L < NL; L++) {
        long wOff = (long)L * DIM * DIM;
        split4_launch(wq + wOff, wqkvh + ((long)L * QKVN + 0)      * DIM,
                                 wqkvl + ((long)L * QKVN + 0)      * DIM, (long)DIM * DIM);
        split4_launch(wk + wOff, wqkvh + ((long)L * QKVN + DIM)    * DIM,
                                 wqkvl + ((long)L * QKVN + DIM)    * DIM, (long)DIM * DIM);
        split4_launch(wv + wOff, wqkvh + ((long)L * QKVN + 2*DIM)  * DIM,
                                 wqkvl + ((long)L * QKVN + 2*DIM)  * DIM, (long)DIM * DIM);
        split4_launch(wo + wOff, woh + wOff, wol + wOff, (long)DIM * DIM);
        long w1Off = (long)L * HIDDEN * DIM;
        split4_launch(w1 + w1Off, w13h + (long)L * N13 * DIM,
                                  w13l + (long)L * N13 * DIM, (long)HIDDEN * DIM);
        split4_launch(w3 + w1Off, w13h + ((long)L * N13 + HIDP) * DIM,
                                  w13l + ((long)L * N13 + HIDP) * DIM, (long)HIDDEN * DIM);
        {
            long n2 = (long)DIM * (HIDP / 2);
            int blocks = (int)((n2 + 255) / 256);
            if (blocks > 4096) blocks = 4096;
            split2_pad_kernel<<<blocks, 256>>>(w2 + (long)L * DIM * HIDDEN,
                (bf162*)(w2h + (long)L * DIM * HIDP), (bf162*)(w2l + (long)L * DIM * HIDP),
                DIM, HIDDEN, HIDP);
        }
    }
    split4_launch(out_w, owh, owl, (long)VOCAB * DIM);

    // ---- forward ----
    embed_kernel<<<(SEQ * DIM + 255) / 256, 256>>>(tokens, emb, h);

    for (int L = 0; L < NL; L++) {
        rmsnorm_split_kernel<<<SEQ, 256>>>(h, attn_nw + L * DIM, xh, xl);

        GEMM_BIG<<<dim3(QKVN / 128, SEQ / 128), 256, SMEM_BIG>>>(
            xh, xl, wqkvh + (long)L * QKVN * DIM, wqkvl + (long)L * QKVN * DIM,
            nullptr, qkv, SEQ, QKVN, DIM);

        rope_kernel<<<(SEQ * NH * (HD / 2) + 255) / 256, 256>>>(qkv);
        attn_kernel<<<dim3(SEQ / BQ, NH), 32 * BQ>>>(qkv, oh, ol);

        GEMM_SMALL<<<dim3(DIM / 64, SEQ / 64), 128, SMEM_SMALL>>>(
            oh, ol, woh + (long)L * DIM * DIM, wol + (long)L * DIM * DIM,
            h, h, SEQ, DIM, DIM);

        rmsnorm_split_kernel<<<SEQ, 256>>>(h, ffn_nw + L * DIM, xh, xl);

        GEMM_BIG<<<dim3(N13 / 128, SEQ / 128), 256, SMEM_BIG>>>(
            xh, xl, w13h + (long)L * N13 * DIM, w13l + (long)L * N13 * DIM,
            nullptr, gg, SEQ, N13, DIM);

        silu_split_kernel<<<(SEQ * HIDDEN + 255) / 256, 256>>>(gg, h1h, h1l);

        GEMM_SMALL<<<dim3(DIM / 64, SEQ / 64), 128, SMEM_SMALL>>>(
            h1h, h1l, w2h + (long)L * DIM * HIDP, w2l + (long)L * DIM * HIDP,
            h, h, SEQ, DIM, HIDP);
    }

    rmsnorm_split_kernel<<<SEQ, 256>>>(h, norm_w, xh, xl);

    GEMM_BIG<<<dim3(VOCAB / 128, SEQ / 128), 256, SMEM_BIG>>>(
        xh, xl, owh, owl, nullptr, out, SEQ, VOCAB, DIM);
}

// round 8
// speedup vs baseline: 2.5513x; 1.0200x over previous
#include <cuda_runtime.h>
#include <cuda_bf16.h>
#include <math.h>
#include <stdint.h>

#define SEQ     2048
#define DIM     768
#define NH      12
#define HD      64
#define HIDDEN  2042
#define HIDP    2048
#define N13     4096
#define QKVN    2304
#define VOCAB   32000
#define NL      4
#define THETA   10000.0f
#define ATT_SCALE 0.125f

typedef __nv_bfloat16 bf16;
typedef __nv_bfloat162 bf162;

// ---------------- fp32 scratch ----------------
__device__ float g_h  [SEQ * DIM];
__device__ float g_qkv[SEQ * QKVN];
__device__ float g_g  [SEQ * N13];

// ---------------- bf16 hi/lo planes (16B aligned) ----------------
__device__ __align__(16) bf16 g_wqkv_h[NL * QKVN * DIM],  g_wqkv_l[NL * QKVN * DIM];
__device__ __align__(16) bf16 g_wo_h  [NL * DIM * DIM],   g_wo_l  [NL * DIM * DIM];
__device__ __align__(16) bf16 g_w13_h [NL * N13 * DIM],   g_w13_l [NL * N13 * DIM];
__device__ __align__(16) bf16 g_w2_h  [NL * DIM * HIDP],  g_w2_l  [NL * DIM * HIDP];
__device__ __align__(16) bf16 g_ow_h  [VOCAB * DIM],      g_ow_l  [VOCAB * DIM];
__device__ __align__(16) bf16 g_xh [SEQ * DIM],  g_xl [SEQ * DIM];
__device__ __align__(16) bf16 g_oh [SEQ * DIM],  g_ol [SEQ * DIM];
__device__ __align__(16) bf16 g_h1h[SEQ * HIDP], g_h1l[SEQ * HIDP];

// ---------------- helpers ----------------
__device__ __forceinline__ void split1(float v, bf16& h, bf16& l) {
    h = __float2bfloat16(v);
    l = __float2bfloat16(v - __bfloat162float(h));
}

__global__ void split4_kernel(const float4* __restrict__ src,
                              bf162* __restrict__ dh, bf162* __restrict__ dl,
                              long n4) {
    long stride = (long)gridDim.x * blockDim.x;
    for (long i = (long)blockIdx.x * blockDim.x + threadIdx.x; i < n4; i += stride) {
        float4 v = src[i];
        bf16 h0, l0, h1, l1, h2, l2, h3, l3;
        split1(v.x, h0, l0); split1(v.y, h1, l1);
        split1(v.z, h2, l2); split1(v.w, h3, l3);
        dh[i * 2]     = __halves2bfloat162(h0, h1);
        dh[i * 2 + 1] = __halves2bfloat162(h2, h3);
        dl[i * 2]     = __halves2bfloat162(l0, l1);
        dl[i * 2 + 1] = __halves2bfloat162(l2, l3);
    }
}

__global__ void split2_pad_kernel(const float* __restrict__ src,
                                  bf162* __restrict__ dh, bf162* __restrict__ dl,
                                  int rows, int Ks, int Kd) {
    long n2 = (long)rows * (Kd / 2);
    long stride = (long)gridDim.x * blockDim.x;
    for (long i = (long)blockIdx.x * blockDim.x + threadIdx.x; i < n2; i += stride) {
        int r  = (int)(i / (Kd / 2));
        int c2 = (int)(i - (long)r * (Kd / 2));
        float2 v = make_float2(0.f, 0.f);
        if (c2 * 2 + 1 < Ks)
            v = *reinterpret_cast<const float2*>(src + (long)r * Ks + c2 * 2);
        bf16 h0, l0, h1, l1;
        split1(v.x, h0, l0); split1(v.y, h1, l1);
        dh[i] = __halves2bfloat162(h0, h1);
        dl[i] = __halves2bfloat162(l0, l1);
    }
}

__global__ void embed_kernel(const int* __restrict__ tokens,
                             const float* __restrict__ emb,
                             float* __restrict__ h) {
    int i = blockIdx.x * blockDim.x + threadIdx.x;
    if (i < SEQ * DIM) {
        int s = i / DIM, d = i - s * DIM;
        h[i] = emb[(long)tokens[s] * DIM + d];
    }
}

__global__ void rmsnorm_split_kernel(const float* __restrict__ x,
                                     const float* __restrict__ w,
                                     bf16* __restrict__ yh, bf16* __restrict__ yl) {
    int row = blockIdx.x;
    const float2* xr = (const float2*)(x + (long)row * DIM);
    const float2* w2p = (const float2*)w;
    float ss = 0.f;
    #pragma unroll
    for (int d = threadIdx.x; d < DIM / 2; d += 256) {
        float2 t = xr[d];
        ss += t.x * t.x + t.y * t.y;
    }
    #pragma unroll
    for (int off = 16; off; off >>= 1) ss += __shfl_xor_sync(0xffffffffu, ss, off);
    __shared__ float sred[8];
    if ((threadIdx.x & 31) == 0) sred[threadIdx.x >> 5] = ss;
    __syncthreads();
    __shared__ float s_inv;
    if (threadIdx.x == 0) {
        float tot = 0.f;
        #pragma unroll
        for (int i = 0; i < 8; i++) tot += sred[i];
        s_inv = rsqrtf(tot / (float)DIM + 1e-6f);
    }
    __syncthreads();
    float inv = s_inv;
    bf162* yh2 = (bf162*)(yh + (long)row * DIM);
    bf162* yl2 = (bf162*)(yl + (long)row * DIM);
    for (int d = threadIdx.x; d < DIM / 2; d += 256) {
        float2 t = xr[d], ww = w2p[d];
        float v0 = t.x * inv * ww.x, v1 = t.y * inv * ww.y;
        bf16 h0, l0, h1, l1;
        split1(v0, h0, l0); split1(v1, h1, l1);
        yh2[d] = __halves2bfloat162(h0, h1);
        yl2[d] = __halves2bfloat162(l0, l1);
    }
}

__global__ void rope_kernel(float* __restrict__ qkv) {
    int i = blockIdx.x * blockDim.x + threadIdx.x;
    if (i >= SEQ * NH * (HD / 2)) return;
    int p  = i % (HD / 2);
    int sh = i / (HD / 2);
    int h  = sh % NH;
    int s  = sh / NH;
    float freq = powf(THETA, -(2.0f * (float)p) / (float)HD);
    float ang  = (float)s * freq;
    float c = cosf(ang), sn = sinf(ang);
    long base = (long)s * QKVN + h * HD + 2 * p;
    float a = qkv[base], b = qkv[base + 1];
    qkv[base]     = a * c - b * sn;
    qkv[base + 1] = a * sn + b * c;
    a = qkv[base + DIM]; b = qkv[base + DIM + 1];
    qkv[base + DIM]     = a * c - b * sn;
    qkv[base + DIM + 1] = a * sn + b * c;
}

// ---------------- flash attention; output split to hi/lo ----------------
#define BQ 16
__global__ __launch_bounds__(32 * BQ)
void attn_kernel(const float* __restrict__ qkv,
                 bf16* __restrict__ ohp, bf16* __restrict__ olp) {
    int h    = blockIdx.y;
    int q0   = blockIdx.x * BQ;
    int warp = threadIdx.x >> 5;
    int lane = threadIdx.x & 31;
    int qi   = q0 + warp;

    __shared__ float Ks[64][HD + 1];
    __shared__ float Vs[64][HD + 1];
    __shared__ float Qs[BQ][HD];

    Qs[warp][lane]      = qkv[(long)qi * QKVN + h * HD + lane];
    Qs[warp][lane + 32] = qkv[(long)qi * QKVN + h * HD + lane + 32];

    float m = -INFINITY, l = 0.f, o0 = 0.f, o1 = 0.f;
    int kend = q0 + BQ;

    for (int t0 = 0; t0 < kend; t0 += 64) {
        __syncthreads();
        for (int idx = threadIdx.x; idx < 64 * HD; idx += 32 * BQ) {
            int kj = idx >> 6, d = idx & 63;
            long row = (long)(t0 + kj) * QKVN + h * HD + d;
            Ks[kj][d] = qkv[row + DIM];
            Vs[kj][d] = qkv[row + 2 * DIM];
        }
        __syncthreads();

        float s0 = 0.f, s1 = 0.f;
        #pragma unroll
        for (int d = 0; d < HD; d++) {
            float qd = Qs[warp][d];
            s0 = fmaf(qd, Ks[lane][d],      s0);
            s1 = fmaf(qd, Ks[lane + 32][d], s1);
        }
        s0 *= ATT_SCALE; s1 *= ATT_SCALE;
        if (t0 + lane      > qi) s0 = -INFINITY;
        if (t0 + lane + 32 > qi) s1 = -INFINITY;

        float mt = fmaxf(s0, s1);
        #pragma unroll
        for (int off = 16; off; off >>= 1)
            mt = fmaxf(mt, __shfl_xor_sync(0xffffffffu, mt, off));
        float mnew  = fmaxf(m, mt);
        float alpha = expf(m - mnew);
        float p0 = expf(s0 - mnew);
        float p1 = expf(s1 - mnew);
        float lsum = p0 + p1;
        #pragma unroll
        for (int off = 16; off; off >>= 1)
            lsum += __shfl_xor_sync(0xffffffffu, lsum, off);
        l = l * alpha + lsum;
        m = mnew;
        o0 *= alpha; o1 *= alpha;

        #pragma unroll
        for (int j = 0; j < 32; j++) {
            float pa = __shfl_sync(0xffffffffu, p0, j);
            float pb = __shfl_sync(0xffffffffu, p1, j);
            o0 = fmaf(pa, Vs[j][lane],           o0);
            o0 = fmaf(pb, Vs[j + 32][lane],      o0);
            o1 = fmaf(pa, Vs[j][lane + 32],      o1);
            o1 = fmaf(pb, Vs[j + 32][lane + 32], o1);
        }
    }
    float inv = 1.f / l;
    float v0 = o0 * inv, v1 = o1 * inv;
    bf16 hh, ll;
    long base = (long)qi * DIM + h * HD;
    split1(v0, hh, ll); ohp[base + lane]      = hh; olp[base + lane]      = ll;
    split1(v1, hh, ll); ohp[base + lane + 32] = hh; olp[base + lane + 32] = ll;
}

__global__ void silu_split_kernel(const float* __restrict__ gg,
                                  bf162* __restrict__ h1h, bf162* __restrict__ h1l) {
    int i = blockIdx.x * blockDim.x + threadIdx.x;   // over SEQ * HIDDEN/2 pairs
    if (i < SEQ * (HIDDEN / 2)) {
        int s = i / (HIDDEN / 2), j2 = i - s * (HIDDEN / 2);
        const float2 a = *(const float2*)(gg + (long)s * N13 + j2 * 2);
        const float2 b = *(const float2*)(gg + (long)s * N13 + HIDP + j2 * 2);
        float v0 = (a.x / (1.f + expf(-a.x))) * b.x;
        float v1 = (a.y / (1.f + expf(-a.y))) * b.y;
        bf16 h0, l0, h1, l1;
        split1(v0, h0, l0); split1(v1, h1, l1);
        long o = (long)s * (HIDP / 2) + j2;
        h1h[o] = __halves2bfloat162(h0, h1);
        h1l[o] = __halves2bfloat162(l0, l1);
    }
}

// zero the pad columns of h1 planes (cols 2042..2047), once per layer
__global__ void h1pad_kernel(bf16* __restrict__ h1h, bf16* __restrict__ h1l) {
    int i = blockIdx.x * blockDim.x + threadIdx.x;   // SEQ * 6
    if (i < SEQ * (HIDP - HIDDEN)) {
        int s = i / (HIDP - HIDDEN), j = i - s * (HIDP - HIDDEN);
        h1h[(long)s * HIDP + HIDDEN + j] = __float2bfloat16(0.f);
        h1l[(long)s * HIDP + HIDDEN + j] = __float2bfloat16(0.f);
    }
}

// ================= templated bf16x3 mma.sync GEMM, 3-stage, swizzled smem =================
__device__ __forceinline__ void mma_bf16(float* d, const uint32_t* a, const uint32_t* b) {
    asm volatile(
        "mma.sync.aligned.m16n8k16.row.col.f32.bf16.bf16.f32 "
        "{%0,%1,%2,%3}, {%4,%5,%6,%7}, {%8,%9}, {%0,%1,%2,%3};"
        : "+f"(d[0]), "+f"(d[1]), "+f"(d[2]), "+f"(d[3])
        : "r"(a[0]), "r"(a[1]), "r"(a[2]), "r"(a[3]), "r"(b[0]), "r"(b[1]));
}
__device__ __forceinline__ void ldmx4(uint32_t* r, uint32_t addr) {
    asm volatile("ldmatrix.sync.aligned.m8n8.x4.shared.b16 {%0,%1,%2,%3}, [%4];"
                 : "=r"(r[0]), "=r"(r[1]), "=r"(r[2]), "=r"(r[3]) : "r"(addr));
}
__device__ __forceinline__ void cpa16(uint32_t dst, const void* src) {
    asm volatile("cp.async.cg.shared.global [%0], [%1], 16;" :: "r"(dst), "l"(src));
}

template<int BM, int WM, int WN, int THREADS, int MAXB, int K>
__global__ __launch_bounds__(THREADS, MAXB)
void gemm_bf3(const bf16* __restrict__ Ah, const bf16* __restrict__ Al,
              const bf16* __restrict__ Bh, const bf16* __restrict__ Bl,
              const float* __restrict__ res, float* __restrict__ C,
              int N) {
    const int BN = BM;
    const int WARPS_N = BN / WN;
    const int MT = WM / 16;
    const int NT = WN / 8;
    const int PB = BM * 64;          // plane bytes
    const int SB = 4 * PB;           // stage bytes
    const int KT = K / 32;

    extern __shared__ char smc[];
    uint32_t sbase = (uint32_t)__cvta_generic_to_shared(smc);

    int bm = blockIdx.y * BM;
    int bn = blockIdx.x * BN;
    int tid  = threadIdx.x;
    int warp = tid >> 5, lane = tid & 31;
    int wm = (warp / WARPS_N) * WM;
    int wn = (warp % WARPS_N) * WN;
    int g  = lane >> 2, tg = lane & 3;
    int rr = lane & 7, q = lane >> 3;

    // ldmatrix per-lane bases
    int aRowL = wm + rr + 8 * (q & 1);
    int bRowL = wn + rr + 8 * (q >> 1);
    uint32_t aRowOff = (uint32_t)aRowL * 64;
    uint32_t bRowOff = (uint32_t)bRowL * 64;
    uint32_t swA = (uint32_t)((aRowL >> 1) & 3);
    uint32_t swB = (uint32_t)((bRowL >> 1) & 3);
    uint32_t cAk[2], cBk[2];
    #pragma unroll
    for (int ks = 0; ks < 2; ks++) {
        cAk[ks] = ((uint32_t)(2 * ks + (q >> 1)) ^ swA) << 4;
        cBk[ks] = ((uint32_t)(2 * ks + (q & 1))  ^ swB) << 4;
    }

    // loader: rows rowE / rowO, chunk ch, for each of 4 planes
    int rowE = tid >> 2, rowO = rowE + BM / 2;
    int ch   = tid & 3;
    uint32_t dstE = (uint32_t)rowE * 64 + (((uint32_t)ch ^ (((uint32_t)rowE >> 1) & 3)) << 4);
    uint32_t dstO = (uint32_t)rowO * 64 + (((uint32_t)ch ^ (((uint32_t)rowO >> 1) & 3)) << 4);
    int offAE = (bm + rowE) * K + ch * 8;
    int offAO = (bm + rowO) * K + ch * 8;
    int offBE = (bn + rowE) * K + ch * 8;
    int offBO = (bn + rowO) * K + ch * 8;

    float acc[MT][NT][4];
    #pragma unroll
    for (int mi = 0; mi < MT; mi++)
        #pragma unroll
        for (int ni = 0; ni < NT; ni++)
            #pragma unroll
            for (int r = 0; r < 4; r++) acc[mi][ni][r] = 0.f;

    auto fill = [&](int s, int k0) {
        uint32_t st = sbase + (uint32_t)s * SB;
        cpa16(st + dstE,          Ah + offAE + k0);
        cpa16(st + dstO,          Ah + offAO + k0);
        cpa16(st + PB + dstE,     Al + offAE + k0);
        cpa16(st + PB + dstO,     Al + offAO + k0);
        cpa16(st + 2 * PB + dstE, Bh + offBE + k0);
        cpa16(st + 2 * PB + dstO, Bh + offBO + k0);
        cpa16(st + 3 * PB + dstE, Bl + offBE + k0);
        cpa16(st + 3 * PB + dstO, Bl + offBO + k0);
        asm volatile("cp.async.commit_group;");
    };

    fill(0, 0);
    fill(1, 32);

    #pragma unroll 3
    for (int kt = 0; kt < KT; kt++) {
        if (kt + 1 < KT) asm volatile("cp.async.wait_group 1;");
        else             asm volatile("cp.async.wait_group 0;");
        __syncthreads();

        if (kt + 2 < KT) fill((kt + 2) % 3, (kt + 2) * 32);

        uint32_t st  = sbase + (uint32_t)(kt % 3) * SB;
        uint32_t pAH = st;
        uint32_t pAL = st + PB;
        uint32_t pBH = st + 2 * PB;
        uint32_t pBL = st + 3 * PB;

        #pragma unroll
        for (int ks = 0; ks < 2; ks++) {
            uint32_t afH[MT][4], bfH[NT][2], bfX[NT][2];
            #pragma unroll
            for (int mi = 0; mi < MT; mi++)
                ldmx4(afH[mi], pAH + aRowOff + (uint32_t)mi * 1024 + cAk[ks]);
            #pragma unroll
            for (int n2 = 0; n2 < NT / 2; n2++) {
                uint32_t t[4];
                ldmx4(t, pBH + bRowOff + (uint32_t)n2 * 1024 + cBk[ks]);
                bfH[2 * n2][0] = t[0]; bfH[2 * n2][1] = t[1];
                bfH[2 * n2 + 1][0] = t[2]; bfH[2 * n2 + 1][1] = t[3];
            }
            #pragma unroll
            for (int mi = 0; mi < MT; mi++)
                #pragma unroll
                for (int ni = 0; ni < NT; ni++)
                    mma_bf16(acc[mi][ni], afH[mi], bfH[ni]);

            #pragma unroll
            for (int n2 = 0; n2 < NT / 2; n2++) {
                uint32_t t[4];
                ldmx4(t, pBL + bRowOff + (uint32_t)n2 * 1024 + cBk[ks]);
                bfX[2 * n2][0] = t[0]; bfX[2 * n2][1] = t[1];
                bfX[2 * n2 + 1][0] = t[2]; bfX[2 * n2 + 1][1] = t[3];
            }
            #pragma unroll
            for (int mi = 0; mi < MT; mi++)
                #pragma unroll
                for (int ni = 0; ni < NT; ni++)
                    mma_bf16(acc[mi][ni], afH[mi], bfX[ni]);

            #pragma unroll
            for (int mi = 0; mi < MT; mi++)
                ldmx4(afH[mi], pAL + aRowOff + (uint32_t)mi * 1024 + cAk[ks]);
            #pragma unroll
            for (int mi = 0; mi < MT; mi++)
                #pragma unroll
                for (int ni = 0; ni < NT; ni++)
                    mma_bf16(acc[mi][ni], afH[mi], bfH[ni]);
        }
    }

    #pragma unroll
    for (int mi = 0; mi < MT; mi++) {
        int row0 = bm + wm + mi * 16 + g;
        #pragma unroll
        for (int ni = 0; ni < NT; ni++) {
            int col = bn + wn + ni * 8 + tg * 2;
            #pragma unroll
            for (int half = 0; half < 2; half++) {
                int row = row0 + half * 8;
                long idx = (long)row * N + col;
                float v0 = acc[mi][ni][half * 2 + 0];
                float v1 = acc[mi][ni][half * 2 + 1];
                if (res) { v0 += res[idx]; v1 += res[idx + 1]; }
                C[idx]     = v0;
                C[idx + 1] = v1;
            }
        }
    }
}

// instantiations
#define GB768   gemm_bf3<128, 64, 32, 256, 2, 768>
#define GS768   gemm_bf3< 64, 32, 32, 128, 4, 768>
#define GS2048  gemm_bf3< 64, 32, 32, 128, 4, 2048>
#define SMEM_B  (3 * 4 * 128 * 64)   // 98304
#define SMEM_S  (3 * 4 * 64 * 64)    // 49152

// ---------------- host launcher ----------------
static inline void split4_launch(const float* src, bf16* dh, bf16* dl, long n) {
    long n4 = n / 4;
    int blocks = (int)((n4 + 255) / 256);
    if (blocks > 4096) blocks = 4096;
    split4_kernel<<<blocks, 256>>>((const float4*)src, (bf162*)dh, (bf162*)dl, n4);
}

extern "C" void kernel_launch(void* const* d_in, const int* in_sizes, int n_in,
                              void* d_out, int out_size) {
    const int*   tokens   = (const int*)  d_in[0];
    const float* emb      = (const float*)d_in[1];
    const float* wq       = (const float*)d_in[2];
    const float* wk       = (const float*)d_in[3];
    const float* wv       = (const float*)d_in[4];
    const float* wo       = (const float*)d_in[5];
    const float* w1       = (const float*)d_in[6];
    const float* w2       = (const float*)d_in[7];
    const float* w3       = (const float*)d_in[8];
    const float* attn_nw  = (const float*)d_in[9];
    const float* ffn_nw   = (const float*)d_in[10];
    const float* norm_w   = (const float*)d_in[11];
    const float* out_w    = (const float*)d_in[12];
    float* out = (float*)d_out;

    float *h, *qkv, *gg;
    cudaGetSymbolAddress((void**)&h,   g_h);
    cudaGetSymbolAddress((void**)&qkv, g_qkv);
    cudaGetSymbolAddress((void**)&gg,  g_g);

    bf16 *wqkvh, *wqkvl, *woh, *wol, *w13h, *w13l, *w2h, *w2l, *owh, *owl;
    bf16 *xh, *xl, *oh, *ol, *h1h, *h1l;
    cudaGetSymbolAddress((void**)&wqkvh, g_wqkv_h); cudaGetSymbolAddress((void**)&wqkvl, g_wqkv_l);
    cudaGetSymbolAddress((void**)&woh,   g_wo_h);   cudaGetSymbolAddress((void**)&wol,   g_wo_l);
    cudaGetSymbolAddress((void**)&w13h,  g_w13_h);  cudaGetSymbolAddress((void**)&w13l,  g_w13_l);
    cudaGetSymbolAddress((void**)&w2h,   g_w2_h);   cudaGetSymbolAddress((void**)&w2l,   g_w2_l);
    cudaGetSymbolAddress((void**)&owh,   g_ow_h);   cudaGetSymbolAddress((void**)&owl,   g_ow_l);
    cudaGetSymbolAddress((void**)&xh,  g_xh);  cudaGetSymbolAddress((void**)&xl,  g_xl);
    cudaGetSymbolAddress((void**)&oh,  g_oh);  cudaGetSymbolAddress((void**)&ol,  g_ol);
    cudaGetSymbolAddress((void**)&h1h, g_h1h); cudaGetSymbolAddress((void**)&h1l, g_h1l);

    cudaFuncSetAttribute(GB768,  cudaFuncAttributeMaxDynamicSharedMemorySize, SMEM_B);
    cudaFuncSetAttribute(GS768,  cudaFuncAttributeMaxDynamicSharedMemorySize, SMEM_S);
    cudaFuncSetAttribute(GS2048, cudaFuncAttributeMaxDynamicSharedMemorySize, SMEM_S);

    // ---- weight conversion ----
    for (int L = 0; L < NL; L++) {
        long wOff = (long)L * DIM * DIM;
        split4_launch(wq + wOff, wqkvh + ((long)L * QKVN + 0)      * DIM,
                                 wqkvl + ((long)L * QKVN + 0)      * DIM, (long)DIM * DIM);
        split4_launch(wk + wOff, wqkvh + ((long)L * QKVN + DIM)    * DIM,
                                 wqkvl + ((long)L * QKVN + DIM)    * DIM, (long)DIM * DIM);
        split4_launch(wv + wOff, wqkvh + ((long)L * QKVN + 2*DIM)  * DIM,
                                 wqkvl + ((long)L * QKVN + 2*DIM)  * DIM, (long)DIM * DIM);
        split4_launch(wo + wOff, woh + wOff, wol + wOff, (long)DIM * DIM);
        long w1Off = (long)L * HIDDEN * DIM;
        split4_launch(w1 + w1Off, w13h + (long)L * N13 * DIM,
                                  w13l + (long)L * N13 * DIM, (long)HIDDEN * DIM);
        split4_launch(w3 + w1Off, w13h + ((long)L * N13 + HIDP) * DIM,
                                  w13l + ((long)L * N13 + HIDP) * DIM, (long)HIDDEN * DIM);
        {
            long n2 = (long)DIM * (HIDP / 2);
            int blocks = (int)((n2 + 255) / 256);
            if (blocks > 4096) blocks = 4096;
            split2_pad_kernel<<<blocks, 256>>>(w2 + (long)L * DIM * HIDDEN,
                (bf162*)(w2h + (long)L * DIM * HIDP), (bf162*)(w2l + (long)L * DIM * HIDP),
                DIM, HIDDEN, HIDP);
        }
    }
    split4_launch(out_w, owh, owl, (long)VOCAB * DIM);

    // ---- forward ----
    embed_kernel<<<(SEQ * DIM + 255) / 256, 256>>>(tokens, emb, h);

    for (int L = 0; L < NL; L++) {
        rmsnorm_split_kernel<<<SEQ, 256>>>(h, attn_nw + L * DIM, xh, xl);

        GB768<<<dim3(QKVN / 128, SEQ / 128), 256, SMEM_B>>>(
            xh, xl, wqkvh + (long)L * QKVN * DIM, wqkvl + (long)L * QKVN * DIM,
            nullptr, qkv, QKVN);

        rope_kernel<<<(SEQ * NH * (HD / 2) + 255) / 256, 256>>>(qkv);
        attn_kernel<<<dim3(SEQ / BQ, NH), 32 * BQ>>>(qkv, oh, ol);

        GS768<<<dim3(DIM / 64, SEQ / 64), 128, SMEM_S>>>(
            oh, ol, woh + (long)L * DIM * DIM, wol + (long)L * DIM * DIM,
            h, h, DIM);

        rmsnorm_split_kernel<<<SEQ, 256>>>(h, ffn_nw + L * DIM, xh, xl);

        GB768<<<dim3(N13 / 128, SEQ / 128), 256, SMEM_B>>>(
            xh, xl, w13h + (long)L * N13 * DIM, w13l + (long)L * N13 * DIM,
            nullptr, gg, N13);

        silu_split_kernel<<<(SEQ * (HIDDEN / 2) + 255) / 256, 256>>>(
            gg, (bf162*)h1h, (bf162*)h1l);
        h1pad_kernel<<<(SEQ * (HIDP - HIDDEN) + 255) / 256, 256>>>(h1h, h1l);

        GS2048<<<dim3(DIM / 64, SEQ / 64), 128, SMEM_S>>>(
            h1h, h1l, w2h + (long)L * DIM * HIDP, w2l + (long)L * DIM * HIDP,
            h, h, DIM);
    }

    rmsnorm_split_kernel<<<SEQ, 256>>>(h, norm_w, xh, xl);

    GB768<<<dim3(VOCAB / 128, SEQ / 128), 256, SMEM_B>>>(
        xh, xl, owh, owl, nullptr, out, VOCAB);
}